// round 4
// baseline (speedup 1.0000x reference)
#include <cuda_runtime.h>
#include <math_constants.h>

#define BATCH 2
#define SEQ   2048
#define DMODEL 1024
#define NHEAD 16
#define DHEAD 64

// Scratch (allocation-free): q,k,v in (B,H,S,DH) layout, x = attention output in (B,S,D)
__device__ float g_q[BATCH*NHEAD*SEQ*DHEAD];
__device__ float g_k[BATCH*NHEAD*SEQ*DHEAD];
__device__ float g_v[BATCH*NHEAD*SEQ*DHEAD];
__device__ float g_x[BATCH*SEQ*DMODEL];

// ---------------------------------------------------------------------------
// GEMM: C = A(MxK) @ W(NxK)^T + bias.  K = 1024 fixed.
// MODE 0: C row-major (M x N).
// MODE 1: head layout: row r=(b*S+s), col c=(h*64+dh) -> ((b*H+h)*S+s)*64+dh
// Tiles 64x64, BK=32, 256 threads, 4x4 micro-tile, transposed smem (k-major).
// ---------------------------------------------------------------------------
template<int MODE>
__global__ void __launch_bounds__(256) gemm_bias_kernel(
    const float* __restrict__ A, const float* __restrict__ W,
    const float* __restrict__ bias, float* __restrict__ C, int N)
{
    const int K = 1024;
    __shared__ float As[32*68];
    __shared__ float Bs[32*68];
    const int tid = threadIdx.x;
    const int tx = tid & 15, ty = tid >> 4;
    const int row0 = blockIdx.y * 64;
    const int col0 = blockIdx.x * 64;

    float acc[4][4] = {};

    for (int k0 = 0; k0 < K; k0 += 32) {
        #pragma unroll
        for (int e = 0; e < 8; e++) {
            int lin = e * 256 + tid;
            int i = lin >> 5, kk = lin & 31;
            As[kk*68 + i] = A[(row0 + i) * K + k0 + kk];
            Bs[kk*68 + i] = W[(col0 + i) * K + k0 + kk];
        }
        __syncthreads();
        const float4* As4 = (const float4*)As;
        const float4* Bs4 = (const float4*)Bs;
        #pragma unroll 16
        for (int kk = 0; kk < 32; kk++) {
            float4 a = As4[kk*17 + ty];
            float4 b = Bs4[kk*17 + tx];
            float av[4] = {a.x, a.y, a.z, a.w};
            float bv[4] = {b.x, b.y, b.z, b.w};
            #pragma unroll
            for (int i = 0; i < 4; i++)
                #pragma unroll
                for (int j = 0; j < 4; j++)
                    acc[i][j] += av[i] * bv[j];
        }
        __syncthreads();
    }

    float4 bb = *(const float4*)&bias[col0 + tx*4];
    float bvv[4] = {bb.x, bb.y, bb.z, bb.w};
    #pragma unroll
    for (int i = 0; i < 4; i++) {
        float4 o;
        o.x = acc[i][0] + bvv[0];
        o.y = acc[i][1] + bvv[1];
        o.z = acc[i][2] + bvv[2];
        o.w = acc[i][3] + bvv[3];
        int r = row0 + ty*4 + i;
        if (MODE == 0) {
            *(float4*)&C[r * N + col0 + tx*4] = o;
        } else {
            int b = r >> 11;            // r / SEQ
            int s = r & (SEQ - 1);
            int h = col0 >> 6;          // col0 is a multiple of 64
            int dst = ((b * NHEAD + h) * SEQ + s) * DHEAD + tx*4;
            *(float4*)&C[dst] = o;
        }
    }
}

// ---------------------------------------------------------------------------
// Flash-style masked attention.
// Grid: (S/64, H, B). Block: 256 threads (16x16), 4x4 micro-tiles.
// Reference semantics: p = softmax(scores*m)*m renormalized ==
//   exp(s_k - max_unmasked) * mask_k / sum  (1e-13 term negligible),
//   and rows with mask[q]==0 output exactly 0.
// ---------------------------------------------------------------------------
__global__ void __launch_bounds__(256) attn_kernel(
    const float* __restrict__ q, const float* __restrict__ kmat,
    const float* __restrict__ v, const float* __restrict__ mask,
    float* __restrict__ xout)
{
    extern __shared__ float sm[];
    float* Qt = sm;                 // [64 d][68] transposed
    float* Kt = Qt + 64*68;         // [64 d][68] transposed
    float* Ps = Kt + 64*68;         // [64 r][68]
    float* Vs = Ps + 64*68;         // [64 k][64 dh]
    float* mk = Vs + 64*64;         // [64]
    float* mq = mk + 64;            // [64]

    const int tid = threadIdx.x;
    const int tx = tid & 15, ty = tid >> 4;
    const int q0 = blockIdx.x * 64;
    const int h  = blockIdx.y;
    const int b  = blockIdx.z;
    const int base = (b * NHEAD + h) * SEQ * DHEAD;
    const float* qb = q + base + q0 * DHEAD;

    // Load Q tile transposed: Qt[d][i] = Q[q0+i][d]
    #pragma unroll
    for (int e = 0; e < 16; e++) {
        int lin = e * 256 + tid;
        int d = lin & 63, i = lin >> 6;
        Qt[d*68 + i] = qb[i * DHEAD + d];
    }
    if (tid < 64) mq[tid] = mask[b * SEQ + q0 + tid];

    float acc[4][4] = {};
    float mrow[4] = {-CUDART_INF_F, -CUDART_INF_F, -CUDART_INF_F, -CUDART_INF_F};
    float lrow[4] = {};

    for (int j0 = 0; j0 < SEQ; j0 += 64) {
        __syncthreads();  // prev GEMM2 done with Ps/Vs; Q load visible on first iter
        const float* kb = kmat + base + j0 * DHEAD;
        const float* vb = v    + base + j0 * DHEAD;
        #pragma unroll
        for (int e = 0; e < 16; e++) {
            int lin = e * 256 + tid;
            int d = lin & 63, i = lin >> 6;
            Kt[d*68 + i] = kb[i * DHEAD + d];
        }
        #pragma unroll
        for (int e = 0; e < 4; e++) {
            int lin = e * 256 + tid;
            ((float4*)Vs)[lin] = ((const float4*)vb)[lin];
        }
        if (tid < 64) mk[tid] = mask[b * SEQ + j0 + tid];
        __syncthreads();

        // GEMM1: scores (64q x 64k), contraction over d
        float sc[4][4] = {};
        {
            const float4* Qt4 = (const float4*)Qt;
            const float4* Kt4 = (const float4*)Kt;
            #pragma unroll 16
            for (int d = 0; d < 64; d++) {
                float4 a = Qt4[d*17 + ty];
                float4 c = Kt4[d*17 + tx];
                float av[4] = {a.x, a.y, a.z, a.w};
                float cv[4] = {c.x, c.y, c.z, c.w};
                #pragma unroll
                for (int i = 0; i < 4; i++)
                    #pragma unroll
                    for (int j = 0; j < 4; j++)
                        sc[i][j] += av[i] * cv[j];
            }
        }

        float msk[4];
        #pragma unroll
        for (int j = 0; j < 4; j++) msk[j] = mk[tx*4 + j];

        float pv[4][4];
        #pragma unroll
        for (int i = 0; i < 4; i++) {
            float rm = -CUDART_INF_F;
            #pragma unroll
            for (int j = 0; j < 4; j++) {
                sc[i][j] *= 0.125f;   // 1/sqrt(64)
                float vv = (msk[j] > 0.f) ? sc[i][j] : -CUDART_INF_F;
                rm = fmaxf(rm, vv);
            }
            #pragma unroll
            for (int o = 8; o >= 1; o >>= 1)
                rm = fmaxf(rm, __shfl_xor_sync(0xffffffffu, rm, o));

            float newm = fmaxf(mrow[i], rm);
            float corr, rs = 0.f;
            if (newm == -CUDART_INF_F) {       // everything masked so far
                corr = 1.f;
                #pragma unroll
                for (int j = 0; j < 4; j++) pv[i][j] = 0.f;
            } else {
                corr = __expf(mrow[i] - newm); // exp(-inf)=0 handles first tile
                #pragma unroll
                for (int j = 0; j < 4; j++) {
                    float p = (msk[j] > 0.f) ? __expf(sc[i][j] - newm) : 0.f;
                    pv[i][j] = p;
                    rs += p;
                }
            }
            #pragma unroll
            for (int o = 8; o >= 1; o >>= 1)
                rs += __shfl_xor_sync(0xffffffffu, rs, o);

            lrow[i] = lrow[i] * corr + rs;
            #pragma unroll
            for (int j = 0; j < 4; j++) acc[i][j] *= corr;
            mrow[i] = newm;
        }

        // Write P tile (row-major, float4, conflict-free)
        {
            float4* Ps4 = (float4*)Ps;
            #pragma unroll
            for (int i = 0; i < 4; i++)
                Ps4[(ty*4 + i)*17 + tx] =
                    make_float4(pv[i][0], pv[i][1], pv[i][2], pv[i][3]);
        }
        __syncthreads();

        // GEMM2: acc += P (64q x 64k) @ V (64k x 64dh)
        {
            const float4* Vs4 = (const float4*)Vs;
            #pragma unroll 16
            for (int kk = 0; kk < 64; kk++) {
                float4 vv = Vs4[kk*16 + tx];
                float vvv[4] = {vv.x, vv.y, vv.z, vv.w};
                #pragma unroll
                for (int i = 0; i < 4; i++) {
                    float p = Ps[(ty*4 + i)*68 + kk];
                    acc[i][0] += p * vvv[0];
                    acc[i][1] += p * vvv[1];
                    acc[i][2] += p * vvv[2];
                    acc[i][3] += p * vvv[3];
                }
            }
        }
    }

    // Finalize: divide by l; masked query rows -> exact 0
    #pragma unroll
    for (int i = 0; i < 4; i++) {
        int r = ty*4 + i;
        float inv = (mq[r] > 0.f && lrow[i] > 0.f) ? (1.0f / lrow[i]) : 0.f;
        float4 o = make_float4(acc[i][0]*inv, acc[i][1]*inv,
                               acc[i][2]*inv, acc[i][3]*inv);
        int srow = q0 + r;
        *(float4*)&xout[(b * SEQ + srow) * DMODEL + h * DHEAD + tx*4] = o;
    }
}

// ---------------------------------------------------------------------------
extern "C" void kernel_launch(void* const* d_in, const int* in_sizes, int n_in,
                              void* d_out, int out_size)
{
    const float* X    = (const float*)d_in[0];
    const float* mask = (const float*)d_in[1];
    const float* Wq   = (const float*)d_in[2];
    const float* bq   = (const float*)d_in[3];
    const float* Wk   = (const float*)d_in[4];
    const float* bk   = (const float*)d_in[5];
    const float* Wv   = (const float*)d_in[6];
    const float* bv   = (const float*)d_in[7];
    const float* Wo   = (const float*)d_in[8];
    const float* bo   = (const float*)d_in[9];
    float* out = (float*)d_out;

    float *gq, *gk, *gv, *gx;
    cudaGetSymbolAddress((void**)&gq, g_q);
    cudaGetSymbolAddress((void**)&gk, g_k);
    cudaGetSymbolAddress((void**)&gv, g_v);
    cudaGetSymbolAddress((void**)&gx, g_x);

    const size_t attn_smem = (3*64*68 + 64*64 + 128) * sizeof(float); // 69632 - pad? = 69120B
    cudaFuncSetAttribute(attn_kernel,
                         cudaFuncAttributeMaxDynamicSharedMemorySize,
                         (int)attn_smem);

    dim3 gproj(DMODEL/64, (BATCH*SEQ)/64);   // (16, 64)
    gemm_bias_kernel<1><<<gproj, 256>>>(X, Wq, bq, gq, DMODEL);
    gemm_bias_kernel<1><<<gproj, 256>>>(X, Wk, bk, gk, DMODEL);
    gemm_bias_kernel<1><<<gproj, 256>>>(X, Wv, bv, gv, DMODEL);

    dim3 gattn(SEQ/64, NHEAD, BATCH);        // (32, 16, 2)
    attn_kernel<<<gattn, 256, attn_smem>>>(gq, gk, gv, mask, gx);

    gemm_bias_kernel<0><<<gproj, 256>>>(gx, Wo, bo, out, DMODEL);
}

// round 8
// speedup vs baseline: 1.5311x; 1.5311x over previous
#include <cuda_runtime.h>
#include <cuda_bf16.h>
#include <math_constants.h>
#include <cstdint>

#define BATCH 2
#define SEQ   2048
#define DMODEL 1024
#define NHEAD 16
#define DHEAD 64

// ---------------------------------------------------------------------------
// Scratch (allocation-free device globals)
// ---------------------------------------------------------------------------
__device__ float g_q[BATCH*NHEAD*SEQ*DHEAD];
__device__ float g_k[BATCH*NHEAD*SEQ*DHEAD];
__device__ float g_v[BATCH*NHEAD*SEQ*DHEAD];
__device__ float g_x[BATCH*SEQ*DMODEL];

// bf16 split planes
__device__ __nv_bfloat16 g_xhi[BATCH*SEQ*DMODEL];
__device__ __nv_bfloat16 g_xlo[BATCH*SEQ*DMODEL];
__device__ __nv_bfloat16 g_wqhi[DMODEL*DMODEL];
__device__ __nv_bfloat16 g_wqlo[DMODEL*DMODEL];
__device__ __nv_bfloat16 g_wkhi[DMODEL*DMODEL];
__device__ __nv_bfloat16 g_wklo[DMODEL*DMODEL];
__device__ __nv_bfloat16 g_wvhi[DMODEL*DMODEL];
__device__ __nv_bfloat16 g_wvlo[DMODEL*DMODEL];
__device__ __nv_bfloat16 g_wohi[DMODEL*DMODEL];
__device__ __nv_bfloat16 g_wolo[DMODEL*DMODEL];
__device__ __nv_bfloat16 g_gxhi[BATCH*SEQ*DMODEL];
__device__ __nv_bfloat16 g_gxlo[BATCH*SEQ*DMODEL];

// ---------------------------------------------------------------------------
// Helpers
// ---------------------------------------------------------------------------
__device__ __forceinline__ uint32_t smem_u32(const void* p) {
    uint32_t a;
    asm("{ .reg .u64 t; cvta.to.shared.u64 t, %1; cvt.u32.u64 %0, t; }"
        : "=r"(a) : "l"(p));
    return a;
}
__device__ __forceinline__ void cp16(uint32_t dst, const void* src) {
    asm volatile("cp.async.cg.shared.global [%0], [%1], 16;"
                 :: "r"(dst), "l"(src) : "memory");
}
__device__ __forceinline__ void cp_commit() {
    asm volatile("cp.async.commit_group;" ::: "memory");
}
template<int N>
__device__ __forceinline__ void cp_wait() {
    asm volatile("cp.async.wait_group %0;" :: "n"(N) : "memory");
}
__device__ __forceinline__ void mma_bf16(float c[4], uint32_t a0, uint32_t a1,
                                         uint32_t a2, uint32_t a3,
                                         uint32_t b0, uint32_t b1) {
    asm volatile(
        "mma.sync.aligned.m16n8k16.row.col.f32.bf16.bf16.f32 "
        "{%0,%1,%2,%3}, {%4,%5,%6,%7}, {%8,%9}, {%0,%1,%2,%3};"
        : "+f"(c[0]), "+f"(c[1]), "+f"(c[2]), "+f"(c[3])
        : "r"(a0), "r"(a1), "r"(a2), "r"(a3), "r"(b0), "r"(b1));
}

// ---------------------------------------------------------------------------
// Split kernel: fp32 -> bf16 hi + bf16 lo residual
// ---------------------------------------------------------------------------
__global__ void __launch_bounds__(256) split_kernel(
    const float* __restrict__ src, __nv_bfloat16* __restrict__ hi,
    __nv_bfloat16* __restrict__ lo, int n4)
{
    int i = blockIdx.x * blockDim.x + threadIdx.x;
    if (i >= n4) return;
    float4 v = ((const float4*)src)[i];
    float vv[4] = {v.x, v.y, v.z, v.w};
    #pragma unroll
    for (int j = 0; j < 4; j++) {
        __nv_bfloat16 h = __float2bfloat16_rn(vv[j]);
        float r = vv[j] - __bfloat162float(h);
        hi[i*4 + j] = h;
        lo[i*4 + j] = __float2bfloat16_rn(r);
    }
}

// ---------------------------------------------------------------------------
// HMMA GEMM: C = A(4096x1024) @ W(1024x1024)^T + bias
// bf16 split precision (hh + hl + lh), fp32 accum via mma.sync m16n8k16.
// CTA tile 128(M) x 256(N), 8 warps of 64x64. K chunks of 32, double-buffered
// cp.async. Smem rows padded to 40 bf16 (conflict-free LDS.32 frag loads).
// MODE 0: row-major out.  MODE 1: head-layout out.
// ---------------------------------------------------------------------------
#define LDK 40
#define ST_AHI 0
#define ST_ALO (128*LDK)
#define ST_BHI (2*128*LDK)
#define ST_BLO (2*128*LDK + 256*LDK)
#define STAGE_ELEMS (2*128*LDK + 2*256*LDK)   // 30720 bf16 = 61440 B

template<int MODE>
__device__ __forceinline__ void gemm_load_stage(
    __nv_bfloat16* sb, int st,
    const __nv_bfloat16* __restrict__ Ahi, const __nv_bfloat16* __restrict__ Alo,
    const __nv_bfloat16* __restrict__ Bhi, const __nv_bfloat16* __restrict__ Blo,
    int m0, int n0, int k0, int tid)
{
    __nv_bfloat16* s = sb + st * STAGE_ELEMS;
    // A: 128 rows x 4 segs(8 bf16) = 512 16B ops each plane -> 2 per thread
    #pragma unroll
    for (int i = 0; i < 2; i++) {
        int lin = i * 256 + tid;
        int r = lin >> 2, seg = lin & 3;
        uint32_t d = smem_u32(s + ST_AHI + r * LDK + seg * 8);
        cp16(d, Ahi + (size_t)(m0 + r) * DMODEL + k0 + seg * 8);
        uint32_t d2 = smem_u32(s + ST_ALO + r * LDK + seg * 8);
        cp16(d2, Alo + (size_t)(m0 + r) * DMODEL + k0 + seg * 8);
    }
    // B: 256 rows x 4 segs = 1024 ops each plane -> 4 per thread
    #pragma unroll
    for (int i = 0; i < 4; i++) {
        int lin = i * 256 + tid;
        int r = lin >> 2, seg = lin & 3;
        uint32_t d = smem_u32(s + ST_BHI + r * LDK + seg * 8);
        cp16(d, Bhi + (size_t)(n0 + r) * DMODEL + k0 + seg * 8);
        uint32_t d2 = smem_u32(s + ST_BLO + r * LDK + seg * 8);
        cp16(d2, Blo + (size_t)(n0 + r) * DMODEL + k0 + seg * 8);
    }
}

template<int MODE>
__global__ void __launch_bounds__(256, 1) mma_gemm(
    const __nv_bfloat16* __restrict__ Ahi, const __nv_bfloat16* __restrict__ Alo,
    const __nv_bfloat16* __restrict__ Bhi, const __nv_bfloat16* __restrict__ Blo,
    const float* __restrict__ bias, float* __restrict__ C)
{
    extern __shared__ __align__(16) __nv_bfloat16 sb[];
    const int tid  = threadIdx.x;
    const int wid  = tid >> 5;
    const int lane = tid & 31;
    const int g    = lane >> 2;       // group 0..7
    const int tig  = lane & 3;        // thread-in-group
    const int m0 = blockIdx.y * 128;
    const int n0 = blockIdx.x * 256;
    const int wm = wid & 1;           // 0..1 -> 64-row slab
    const int wn = wid >> 1;          // 0..3 -> 64-col slab

    float acc[4][8][4];
    #pragma unroll
    for (int mt = 0; mt < 4; mt++)
        #pragma unroll
        for (int nt = 0; nt < 8; nt++)
            #pragma unroll
            for (int r = 0; r < 4; r++) acc[mt][nt][r] = 0.f;

    gemm_load_stage<MODE>(sb, 0, Ahi, Alo, Bhi, Blo, m0, n0, 0, tid);
    cp_commit();

    const int NC = DMODEL / 32;   // 32 chunks
    #pragma unroll 1
    for (int c = 0; c < NC; c++) {
        if (c + 1 < NC) {
            gemm_load_stage<MODE>(sb, (c + 1) & 1, Ahi, Alo, Bhi, Blo,
                                  m0, n0, (c + 1) * 32, tid);
            cp_commit();
            cp_wait<1>();
        } else {
            cp_wait<0>();
        }
        __syncthreads();

        const __nv_bfloat16* s = sb + (c & 1) * STAGE_ELEMS;
        const __nv_bfloat16* sAh = s + ST_AHI;
        const __nv_bfloat16* sAl = s + ST_ALO;
        const __nv_bfloat16* sBh = s + ST_BHI;
        const __nv_bfloat16* sBl = s + ST_BLO;

        #pragma unroll
        for (int sstep = 0; sstep < 2; sstep++) {
            const int koff = sstep * 16;
            uint32_t a[4][4], al[4][4], b[8][2];
            #pragma unroll
            for (int mt = 0; mt < 4; mt++) {
                int base = (wm*64 + mt*16 + g) * LDK + koff + tig*2;
                a[mt][0] = *(const uint32_t*)(sAh + base);
                a[mt][1] = *(const uint32_t*)(sAh + base + 8*LDK);
                a[mt][2] = *(const uint32_t*)(sAh + base + 8);
                a[mt][3] = *(const uint32_t*)(sAh + base + 8*LDK + 8);
            }
            #pragma unroll
            for (int nt = 0; nt < 8; nt++) {
                int nb = (wn*64 + nt*8 + g) * LDK + koff + tig*2;
                b[nt][0] = *(const uint32_t*)(sBh + nb);
                b[nt][1] = *(const uint32_t*)(sBh + nb + 8);
            }
            // hh
            #pragma unroll
            for (int mt = 0; mt < 4; mt++)
                #pragma unroll
                for (int nt = 0; nt < 8; nt++)
                    mma_bf16(acc[mt][nt], a[mt][0], a[mt][1], a[mt][2], a[mt][3],
                             b[nt][0], b[nt][1]);
            // lh: A-lo x B-hi
            #pragma unroll
            for (int mt = 0; mt < 4; mt++) {
                int base = (wm*64 + mt*16 + g) * LDK + koff + tig*2;
                al[mt][0] = *(const uint32_t*)(sAl + base);
                al[mt][1] = *(const uint32_t*)(sAl + base + 8*LDK);
                al[mt][2] = *(const uint32_t*)(sAl + base + 8);
                al[mt][3] = *(const uint32_t*)(sAl + base + 8*LDK + 8);
            }
            #pragma unroll
            for (int mt = 0; mt < 4; mt++)
                #pragma unroll
                for (int nt = 0; nt < 8; nt++)
                    mma_bf16(acc[mt][nt], al[mt][0], al[mt][1], al[mt][2], al[mt][3],
                             b[nt][0], b[nt][1]);
            // hl: A-hi x B-lo (reuse b regs)
            #pragma unroll
            for (int nt = 0; nt < 8; nt++) {
                int nb = (wn*64 + nt*8 + g) * LDK + koff + tig*2;
                b[nt][0] = *(const uint32_t*)(sBl + nb);
                b[nt][1] = *(const uint32_t*)(sBl + nb + 8);
            }
            #pragma unroll
            for (int mt = 0; mt < 4; mt++)
                #pragma unroll
                for (int nt = 0; nt < 8; nt++)
                    mma_bf16(acc[mt][nt], a[mt][0], a[mt][1], a[mt][2], a[mt][3],
                             b[nt][0], b[nt][1]);
        }
        __syncthreads();
    }

    // Epilogue: bias + store (two rows per fragment, float2 per pair)
    #pragma unroll
    for (int mt = 0; mt < 4; mt++) {
        #pragma unroll
        for (int nt = 0; nt < 8; nt++) {
            int col = n0 + wn*64 + nt*8 + tig*2;
            float2 bb = *(const float2*)(bias + col);
            int row = m0 + wm*64 + mt*16 + g;
            float2 o0 = make_float2(acc[mt][nt][0] + bb.x, acc[mt][nt][1] + bb.y);
            float2 o1 = make_float2(acc[mt][nt][2] + bb.x, acc[mt][nt][3] + bb.y);
            if (MODE == 0) {
                *(float2*)(C + (size_t)row * DMODEL + col) = o0;
                *(float2*)(C + (size_t)(row + 8) * DMODEL + col) = o1;
            } else {
                int h = col >> 6, dh = col & 63;
                int b0i = row >> 11, s0 = row & (SEQ - 1);
                int b1i = (row + 8) >> 11, s1 = (row + 8) & (SEQ - 1);
                *(float2*)(C + (((size_t)(b0i*NHEAD + h)*SEQ + s0)*DHEAD + dh)) = o0;
                *(float2*)(C + (((size_t)(b1i*NHEAD + h)*SEQ + s1)*DHEAD + dh)) = o1;
            }
        }
    }
}

// ---------------------------------------------------------------------------
// Flash-style masked attention (unchanged: at fp32 FMA roof, proven correct)
// ---------------------------------------------------------------------------
__global__ void __launch_bounds__(256) attn_kernel(
    const float* __restrict__ q, const float* __restrict__ kmat,
    const float* __restrict__ v, const float* __restrict__ mask,
    float* __restrict__ xout)
{
    extern __shared__ float smf[];
    float* Qt = smf;
    float* Kt = Qt + 64*68;
    float* Ps = Kt + 64*68;
    float* Vs = Ps + 64*68;
    float* mk = Vs + 64*64;
    float* mq = mk + 64;

    const int tid = threadIdx.x;
    const int tx = tid & 15, ty = tid >> 4;
    const int q0 = blockIdx.x * 64;
    const int h  = blockIdx.y;
    const int b  = blockIdx.z;
    const int base = (b * NHEAD + h) * SEQ * DHEAD;
    const float* qb = q + base + q0 * DHEAD;

    #pragma unroll
    for (int e = 0; e < 16; e++) {
        int lin = e * 256 + tid;
        int d = lin & 63, i = lin >> 6;
        Qt[d*68 + i] = qb[i * DHEAD + d];
    }
    if (tid < 64) mq[tid] = mask[b * SEQ + q0 + tid];

    float acc[4][4] = {};
    float mrow[4] = {-CUDART_INF_F, -CUDART_INF_F, -CUDART_INF_F, -CUDART_INF_F};
    float lrow[4] = {};

    for (int j0 = 0; j0 < SEQ; j0 += 64) {
        __syncthreads();
        const float* kb = kmat + base + j0 * DHEAD;
        const float* vb = v    + base + j0 * DHEAD;
        #pragma unroll
        for (int e = 0; e < 16; e++) {
            int lin = e * 256 + tid;
            int d = lin & 63, i = lin >> 6;
            Kt[d*68 + i] = kb[i * DHEAD + d];
        }
        #pragma unroll
        for (int e = 0; e < 4; e++) {
            int lin = e * 256 + tid;
            ((float4*)Vs)[lin] = ((const float4*)vb)[lin];
        }
        if (tid < 64) mk[tid] = mask[b * SEQ + j0 + tid];
        __syncthreads();

        float sc[4][4] = {};
        {
            const float4* Qt4 = (const float4*)Qt;
            const float4* Kt4 = (const float4*)Kt;
            #pragma unroll 16
            for (int d = 0; d < 64; d++) {
                float4 a = Qt4[d*17 + ty];
                float4 c = Kt4[d*17 + tx];
                float av[4] = {a.x, a.y, a.z, a.w};
                float cv[4] = {c.x, c.y, c.z, c.w};
                #pragma unroll
                for (int i = 0; i < 4; i++)
                    #pragma unroll
                    for (int j = 0; j < 4; j++)
                        sc[i][j] += av[i] * cv[j];
            }
        }

        float msk[4];
        #pragma unroll
        for (int j = 0; j < 4; j++) msk[j] = mk[tx*4 + j];

        float pv[4][4];
        #pragma unroll
        for (int i = 0; i < 4; i++) {
            float rm = -CUDART_INF_F;
            #pragma unroll
            for (int j = 0; j < 4; j++) {
                sc[i][j] *= 0.125f;
                float vv = (msk[j] > 0.f) ? sc[i][j] : -CUDART_INF_F;
                rm = fmaxf(rm, vv);
            }
            #pragma unroll
            for (int o = 8; o >= 1; o >>= 1)
                rm = fmaxf(rm, __shfl_xor_sync(0xffffffffu, rm, o));

            float newm = fmaxf(mrow[i], rm);
            float corr, rs = 0.f;
            if (newm == -CUDART_INF_F) {
                corr = 1.f;
                #pragma unroll
                for (int j = 0; j < 4; j++) pv[i][j] = 0.f;
            } else {
                corr = __expf(mrow[i] - newm);
                #pragma unroll
                for (int j = 0; j < 4; j++) {
                    float p = (msk[j] > 0.f) ? __expf(sc[i][j] - newm) : 0.f;
                    pv[i][j] = p;
                    rs += p;
                }
            }
            #pragma unroll
            for (int o = 8; o >= 1; o >>= 1)
                rs += __shfl_xor_sync(0xffffffffu, rs, o);

            lrow[i] = lrow[i] * corr + rs;
            #pragma unroll
            for (int j = 0; j < 4; j++) acc[i][j] *= corr;
            mrow[i] = newm;
        }

        {
            float4* Ps4 = (float4*)Ps;
            #pragma unroll
            for (int i = 0; i < 4; i++)
                Ps4[(ty*4 + i)*17 + tx] =
                    make_float4(pv[i][0], pv[i][1], pv[i][2], pv[i][3]);
        }
        __syncthreads();

        {
            const float4* Vs4 = (const float4*)Vs;
            #pragma unroll 16
            for (int kk = 0; kk < 64; kk++) {
                float4 vv = Vs4[kk*16 + tx];
                float vvv[4] = {vv.x, vv.y, vv.z, vv.w};
                #pragma unroll
                for (int i = 0; i < 4; i++) {
                    float p = Ps[(ty*4 + i)*68 + kk];
                    acc[i][0] += p * vvv[0];
                    acc[i][1] += p * vvv[1];
                    acc[i][2] += p * vvv[2];
                    acc[i][3] += p * vvv[3];
                }
            }
        }
    }

    #pragma unroll
    for (int i = 0; i < 4; i++) {
        int r = ty*4 + i;
        float inv = (mq[r] > 0.f && lrow[i] > 0.f) ? (1.0f / lrow[i]) : 0.f;
        float4 o = make_float4(acc[i][0]*inv, acc[i][1]*inv,
                               acc[i][2]*inv, acc[i][3]*inv);
        int srow = q0 + r;
        *(float4*)&xout[(b * SEQ + srow) * DMODEL + h * DHEAD + tx*4] = o;
    }
}

// ---------------------------------------------------------------------------
extern "C" void kernel_launch(void* const* d_in, const int* in_sizes, int n_in,
                              void* d_out, int out_size)
{
    const float* X    = (const float*)d_in[0];
    const float* mask = (const float*)d_in[1];
    const float* Wq   = (const float*)d_in[2];
    const float* bq   = (const float*)d_in[3];
    const float* Wk   = (const float*)d_in[4];
    const float* bk   = (const float*)d_in[5];
    const float* Wv   = (const float*)d_in[6];
    const float* bv   = (const float*)d_in[7];
    const float* Wo   = (const float*)d_in[8];
    const float* bo   = (const float*)d_in[9];
    float* out = (float*)d_out;

    float *gq, *gk, *gv, *gx;
    cudaGetSymbolAddress((void**)&gq, g_q);
    cudaGetSymbolAddress((void**)&gk, g_k);
    cudaGetSymbolAddress((void**)&gv, g_v);
    cudaGetSymbolAddress((void**)&gx, g_x);

    __nv_bfloat16 *xhi, *xlo, *wqh, *wql, *wkh, *wkl, *wvh, *wvl, *woh, *wol, *gxh, *gxl;
    cudaGetSymbolAddress((void**)&xhi, g_xhi);
    cudaGetSymbolAddress((void**)&xlo, g_xlo);
    cudaGetSymbolAddress((void**)&wqh, g_wqhi);
    cudaGetSymbolAddress((void**)&wql, g_wqlo);
    cudaGetSymbolAddress((void**)&wkh, g_wkhi);
    cudaGetSymbolAddress((void**)&wkl, g_wklo);
    cudaGetSymbolAddress((void**)&wvh, g_wvhi);
    cudaGetSymbolAddress((void**)&wvl, g_wvlo);
    cudaGetSymbolAddress((void**)&woh, g_wohi);
    cudaGetSymbolAddress((void**)&wol, g_wolo);
    cudaGetSymbolAddress((void**)&gxh, g_gxhi);
    cudaGetSymbolAddress((void**)&gxl, g_gxlo);

    const int gemm_smem = 2 * STAGE_ELEMS * 2;   // 122880 bytes
    cudaFuncSetAttribute(mma_gemm<0>, cudaFuncAttributeMaxDynamicSharedMemorySize, gemm_smem);
    cudaFuncSetAttribute(mma_gemm<1>, cudaFuncAttributeMaxDynamicSharedMemorySize, gemm_smem);

    const size_t attn_smem = (3*64*68 + 64*64 + 128) * sizeof(float);
    cudaFuncSetAttribute(attn_kernel, cudaFuncAttributeMaxDynamicSharedMemorySize, (int)attn_smem);

    const int nX4 = BATCH*SEQ*DMODEL/4;
    const int nW4 = DMODEL*DMODEL/4;
    split_kernel<<<nX4/256, 256>>>(X,  xhi, xlo, nX4);
    split_kernel<<<nW4/256, 256>>>(Wq, wqh, wql, nW4);
    split_kernel<<<nW4/256, 256>>>(Wk, wkh, wkl, nW4);
    split_kernel<<<nW4/256, 256>>>(Wv, wvh, wvl, nW4);
    split_kernel<<<nW4/256, 256>>>(Wo, woh, wol, nW4);

    dim3 gg(DMODEL/256, (BATCH*SEQ)/128);   // (4, 32)
    mma_gemm<1><<<gg, 256, gemm_smem>>>(xhi, xlo, wqh, wql, bq, gq);
    mma_gemm<1><<<gg, 256, gemm_smem>>>(xhi, xlo, wkh, wkl, bk, gk);
    mma_gemm<1><<<gg, 256, gemm_smem>>>(xhi, xlo, wvh, wvl, bv, gv);

    dim3 gattn(SEQ/64, NHEAD, BATCH);
    attn_kernel<<<gattn, 256, attn_smem>>>(gq, gk, gv, mask, gx);

    split_kernel<<<nX4/256, 256>>>(gx, gxh, gxl, nX4);
    mma_gemm<0><<<gg, 256, gemm_smem>>>(gxh, gxl, woh, wol, bo, out);
}

// round 11
// speedup vs baseline: 2.9464x; 1.9244x over previous
#include <cuda_runtime.h>
#include <cuda_bf16.h>
#include <math_constants.h>
#include <cstdint>

#define BATCH 2
#define SEQ   2048
#define DMODEL 1024
#define NHEAD 16
#define DHEAD 64

// ---------------------------------------------------------------------------
// Scratch (allocation-free device globals)
// ---------------------------------------------------------------------------
__device__ float g_x[BATCH*SEQ*DMODEL];

// bf16 split planes (GEMM inputs)
__device__ __nv_bfloat16 g_xhi[BATCH*SEQ*DMODEL];
__device__ __nv_bfloat16 g_xlo[BATCH*SEQ*DMODEL];
__device__ __nv_bfloat16 g_wqhi[DMODEL*DMODEL];
__device__ __nv_bfloat16 g_wqlo[DMODEL*DMODEL];
__device__ __nv_bfloat16 g_wkhi[DMODEL*DMODEL];
__device__ __nv_bfloat16 g_wklo[DMODEL*DMODEL];
__device__ __nv_bfloat16 g_wvhi[DMODEL*DMODEL];
__device__ __nv_bfloat16 g_wvlo[DMODEL*DMODEL];
__device__ __nv_bfloat16 g_wohi[DMODEL*DMODEL];
__device__ __nv_bfloat16 g_wolo[DMODEL*DMODEL];
__device__ __nv_bfloat16 g_gxhi[BATCH*SEQ*DMODEL];
__device__ __nv_bfloat16 g_gxlo[BATCH*SEQ*DMODEL];

// Q/K/V bf16 hi/lo planes, head layout [b,h,s,dh]
#define QKV_ELEMS (BATCH*NHEAD*SEQ*DHEAD)
__device__ __nv_bfloat16 g_qhi[QKV_ELEMS];
__device__ __nv_bfloat16 g_qlo[QKV_ELEMS];
__device__ __nv_bfloat16 g_khi[QKV_ELEMS];
__device__ __nv_bfloat16 g_klo[QKV_ELEMS];
__device__ __nv_bfloat16 g_vhi[QKV_ELEMS];
__device__ __nv_bfloat16 g_vlo[QKV_ELEMS];

// ---------------------------------------------------------------------------
// Helpers
// ---------------------------------------------------------------------------
__device__ __forceinline__ uint32_t smem_u32(const void* p) {
    uint32_t a;
    asm("{ .reg .u64 t; cvta.to.shared.u64 t, %1; cvt.u32.u64 %0, t; }"
        : "=r"(a) : "l"(p));
    return a;
}
__device__ __forceinline__ void cp16(uint32_t dst, const void* src) {
    asm volatile("cp.async.cg.shared.global [%0], [%1], 16;"
                 :: "r"(dst), "l"(src) : "memory");
}
__device__ __forceinline__ void cp_commit() {
    asm volatile("cp.async.commit_group;" ::: "memory");
}
template<int N>
__device__ __forceinline__ void cp_wait() {
    asm volatile("cp.async.wait_group %0;" :: "n"(N) : "memory");
}
__device__ __forceinline__ void mma_bf16(float c[4], uint32_t a0, uint32_t a1,
                                         uint32_t a2, uint32_t a3,
                                         uint32_t b0, uint32_t b1) {
    asm volatile(
        "mma.sync.aligned.m16n8k16.row.col.f32.bf16.bf16.f32 "
        "{%0,%1,%2,%3}, {%4,%5,%6,%7}, {%8,%9}, {%0,%1,%2,%3};"
        : "+f"(c[0]), "+f"(c[1]), "+f"(c[2]), "+f"(c[3])
        : "r"(a0), "r"(a1), "r"(a2), "r"(a3), "r"(b0), "r"(b1));
}
__device__ __forceinline__ void mma_bf16a(float c[4], const uint32_t a[4],
                                          uint32_t b0, uint32_t b1) {
    mma_bf16(c, a[0], a[1], a[2], a[3], b0, b1);
}
#define LDSM4T(r0,r1,r2,r3,addr) \
    asm volatile("ldmatrix.sync.aligned.m8n8.x4.trans.shared.b16 {%0,%1,%2,%3}, [%4];" \
        : "=r"(r0),"=r"(r1),"=r"(r2),"=r"(r3) : "r"(addr))

__device__ __forceinline__ float ex2f(float x) {
    float r; asm("ex2.approx.f32 %0, %1;" : "=f"(r) : "f"(x)); return r;
}
// pack (x -> low half, y -> high half) to bf16x2; also residual pack
__device__ __forceinline__ uint32_t pack_bf16x2(float x, float y) {
    uint32_t r;
    asm("cvt.rn.bf16x2.f32 %0, %1, %2;" : "=r"(r) : "f"(y), "f"(x));
    return r;
}
__device__ __forceinline__ void pack_hilo(float x, float y,
                                          uint32_t& hi, uint32_t& lo) {
    hi = pack_bf16x2(x, y);
    float hx = __uint_as_float(hi << 16);
    float hy = __uint_as_float(hi & 0xffff0000u);
    lo = pack_bf16x2(x - hx, y - hy);
}

// ---------------------------------------------------------------------------
// Split kernel: fp32 -> bf16 hi + bf16 lo residual
// ---------------------------------------------------------------------------
__global__ void __launch_bounds__(256) split_kernel(
    const float* __restrict__ src, __nv_bfloat16* __restrict__ hi,
    __nv_bfloat16* __restrict__ lo, int n4)
{
    int i = blockIdx.x * blockDim.x + threadIdx.x;
    if (i >= n4) return;
    float4 v = ((const float4*)src)[i];
    float vv[4] = {v.x, v.y, v.z, v.w};
    #pragma unroll
    for (int j = 0; j < 4; j++) {
        __nv_bfloat16 h = __float2bfloat16_rn(vv[j]);
        float r = vv[j] - __bfloat162float(h);
        hi[i*4 + j] = h;
        lo[i*4 + j] = __float2bfloat16_rn(r);
    }
}

// ---------------------------------------------------------------------------
// HMMA GEMM (validated round 8): C = A @ W^T + bias, bf16 split (hh+hl+lh).
// MODE 0: fp32 row-major out.  MODE 2: bf16 hi/lo head-layout out.
// ---------------------------------------------------------------------------
#define LDK 40
#define ST_AHI 0
#define ST_ALO (128*LDK)
#define ST_BHI (2*128*LDK)
#define ST_BLO (2*128*LDK + 256*LDK)
#define STAGE_ELEMS (2*128*LDK + 2*256*LDK)   // 30720 bf16 = 61440 B

__device__ __forceinline__ void gemm_load_stage(
    __nv_bfloat16* sb, int st,
    const __nv_bfloat16* __restrict__ Ahi, const __nv_bfloat16* __restrict__ Alo,
    const __nv_bfloat16* __restrict__ Bhi, const __nv_bfloat16* __restrict__ Blo,
    int m0, int n0, int k0, int tid)
{
    __nv_bfloat16* s = sb + st * STAGE_ELEMS;
    #pragma unroll
    for (int i = 0; i < 2; i++) {
        int lin = i * 256 + tid;
        int r = lin >> 2, seg = lin & 3;
        cp16(smem_u32(s + ST_AHI + r * LDK + seg * 8),
             Ahi + (size_t)(m0 + r) * DMODEL + k0 + seg * 8);
        cp16(smem_u32(s + ST_ALO + r * LDK + seg * 8),
             Alo + (size_t)(m0 + r) * DMODEL + k0 + seg * 8);
    }
    #pragma unroll
    for (int i = 0; i < 4; i++) {
        int lin = i * 256 + tid;
        int r = lin >> 2, seg = lin & 3;
        cp16(smem_u32(s + ST_BHI + r * LDK + seg * 8),
             Bhi + (size_t)(n0 + r) * DMODEL + k0 + seg * 8);
        cp16(smem_u32(s + ST_BLO + r * LDK + seg * 8),
             Blo + (size_t)(n0 + r) * DMODEL + k0 + seg * 8);
    }
}

template<int MODE>
__global__ void __launch_bounds__(256, 1) mma_gemm(
    const __nv_bfloat16* __restrict__ Ahi, const __nv_bfloat16* __restrict__ Alo,
    const __nv_bfloat16* __restrict__ Bhi, const __nv_bfloat16* __restrict__ Blo,
    const float* __restrict__ bias, float* __restrict__ C,
    __nv_bfloat16* __restrict__ Chi, __nv_bfloat16* __restrict__ Clo)
{
    extern __shared__ __align__(16) __nv_bfloat16 sb[];
    const int tid  = threadIdx.x;
    const int lane = tid & 31;
    const int g    = lane >> 2;
    const int tig  = lane & 3;
    const int m0 = blockIdx.y * 128;
    const int n0 = blockIdx.x * 256;
    const int wm = (tid >> 5) & 1;
    const int wn = (tid >> 5) >> 1;

    float acc[4][8][4];
    #pragma unroll
    for (int mt = 0; mt < 4; mt++)
        #pragma unroll
        for (int nt = 0; nt < 8; nt++)
            #pragma unroll
            for (int r = 0; r < 4; r++) acc[mt][nt][r] = 0.f;

    gemm_load_stage(sb, 0, Ahi, Alo, Bhi, Blo, m0, n0, 0, tid);
    cp_commit();

    const int NC = DMODEL / 32;
    #pragma unroll 1
    for (int c = 0; c < NC; c++) {
        if (c + 1 < NC) {
            gemm_load_stage(sb, (c + 1) & 1, Ahi, Alo, Bhi, Blo,
                            m0, n0, (c + 1) * 32, tid);
            cp_commit();
            cp_wait<1>();
        } else {
            cp_wait<0>();
        }
        __syncthreads();

        const __nv_bfloat16* s = sb + (c & 1) * STAGE_ELEMS;
        const __nv_bfloat16* sAh = s + ST_AHI;
        const __nv_bfloat16* sAl = s + ST_ALO;
        const __nv_bfloat16* sBh = s + ST_BHI;
        const __nv_bfloat16* sBl = s + ST_BLO;

        #pragma unroll
        for (int sstep = 0; sstep < 2; sstep++) {
            const int koff = sstep * 16;
            uint32_t a[4][4], al[4][4], b[8][2];
            #pragma unroll
            for (int mt = 0; mt < 4; mt++) {
                int base = (wm*64 + mt*16 + g) * LDK + koff + tig*2;
                a[mt][0] = *(const uint32_t*)(sAh + base);
                a[mt][1] = *(const uint32_t*)(sAh + base + 8*LDK);
                a[mt][2] = *(const uint32_t*)(sAh + base + 8);
                a[mt][3] = *(const uint32_t*)(sAh + base + 8*LDK + 8);
            }
            #pragma unroll
            for (int nt = 0; nt < 8; nt++) {
                int nb = (wn*64 + nt*8 + g) * LDK + koff + tig*2;
                b[nt][0] = *(const uint32_t*)(sBh + nb);
                b[nt][1] = *(const uint32_t*)(sBh + nb + 8);
            }
            #pragma unroll
            for (int mt = 0; mt < 4; mt++)
                #pragma unroll
                for (int nt = 0; nt < 8; nt++)
                    mma_bf16(acc[mt][nt], a[mt][0], a[mt][1], a[mt][2], a[mt][3],
                             b[nt][0], b[nt][1]);
            #pragma unroll
            for (int mt = 0; mt < 4; mt++) {
                int base = (wm*64 + mt*16 + g) * LDK + koff + tig*2;
                al[mt][0] = *(const uint32_t*)(sAl + base);
                al[mt][1] = *(const uint32_t*)(sAl + base + 8*LDK);
                al[mt][2] = *(const uint32_t*)(sAl + base + 8);
                al[mt][3] = *(const uint32_t*)(sAl + base + 8*LDK + 8);
            }
            #pragma unroll
            for (int mt = 0; mt < 4; mt++)
                #pragma unroll
                for (int nt = 0; nt < 8; nt++)
                    mma_bf16(acc[mt][nt], al[mt][0], al[mt][1], al[mt][2], al[mt][3],
                             b[nt][0], b[nt][1]);
            #pragma unroll
            for (int nt = 0; nt < 8; nt++) {
                int nb = (wn*64 + nt*8 + g) * LDK + koff + tig*2;
                b[nt][0] = *(const uint32_t*)(sBl + nb);
                b[nt][1] = *(const uint32_t*)(sBl + nb + 8);
            }
            #pragma unroll
            for (int mt = 0; mt < 4; mt++)
                #pragma unroll
                for (int nt = 0; nt < 8; nt++)
                    mma_bf16(acc[mt][nt], a[mt][0], a[mt][1], a[mt][2], a[mt][3],
                             b[nt][0], b[nt][1]);
        }
        __syncthreads();
    }

    #pragma unroll
    for (int mt = 0; mt < 4; mt++) {
        #pragma unroll
        for (int nt = 0; nt < 8; nt++) {
            int col = n0 + wn*64 + nt*8 + tig*2;
            float2 bb = *(const float2*)(bias + col);
            int row = m0 + wm*64 + mt*16 + g;
            float2 o0 = make_float2(acc[mt][nt][0] + bb.x, acc[mt][nt][1] + bb.y);
            float2 o1 = make_float2(acc[mt][nt][2] + bb.x, acc[mt][nt][3] + bb.y);
            if (MODE == 0) {
                *(float2*)(C + (size_t)row * DMODEL + col) = o0;
                *(float2*)(C + (size_t)(row + 8) * DMODEL + col) = o1;
            } else {
                int h = col >> 6, dh = col & 63;
                int b0i = row >> 11, s0 = row & (SEQ - 1);
                int b1i = (row + 8) >> 11, s1 = (row + 8) & (SEQ - 1);
                size_t i0 = ((size_t)(b0i*NHEAD + h)*SEQ + s0)*DHEAD + dh;
                size_t i1 = ((size_t)(b1i*NHEAD + h)*SEQ + s1)*DHEAD + dh;
                uint32_t phi, plo;
                pack_hilo(o0.x, o0.y, phi, plo);
                *(uint32_t*)(Chi + i0) = phi;
                *(uint32_t*)(Clo + i0) = plo;
                pack_hilo(o1.x, o1.y, phi, plo);
                *(uint32_t*)(Chi + i1) = phi;
                *(uint32_t*)(Clo + i1) = plo;
            }
        }
    }
}

// ---------------------------------------------------------------------------
// HMMA flash attention, bf16 split precision (3 MMA terms per product).
// Grid (S/128, H, B), 256 threads = 8 warps x 16 q-rows (FA2 row-in-warp).
// Scores in log2 domain; mask folded to additive 0/-inf.
// ---------------------------------------------------------------------------
#define LQ 72                       // smem pitch (bf16) for 64-wide tiles
#define S_QH 0
#define S_QL (128*LQ)               // 9216
#define S_STG (2*128*LQ)            // 18432
#define ASTG  (4*128*LQ)            // 36864 elems per K/V stage
#define SM_BF16_ELEMS (S_STG + 2*ASTG)   // 92160
#define SCL2E 0.1803368801111244f   // 0.125 * log2(e)

__global__ void __launch_bounds__(256, 1) attn_mma_kernel(
    const __nv_bfloat16* __restrict__ qhi, const __nv_bfloat16* __restrict__ qlo,
    const __nv_bfloat16* __restrict__ khi, const __nv_bfloat16* __restrict__ klo,
    const __nv_bfloat16* __restrict__ vhi, const __nv_bfloat16* __restrict__ vlo,
    const float* __restrict__ mask, float* __restrict__ xout)
{
    extern __shared__ __align__(16) __nv_bfloat16 sm[];
    float* fsec  = (float*)(sm + SM_BF16_ELEMS);
    float* madds = fsec;          // [2][128]
    float* mqs   = fsec + 256;    // [128]

    const int tid  = threadIdx.x;
    const int w    = tid >> 5;
    const int lane = tid & 31;
    const int g    = lane >> 2;
    const int tig  = lane & 3;
    const int q0 = blockIdx.x * 128;
    const int h  = blockIdx.y;
    const int b  = blockIdx.z;
    const size_t hb = ((size_t)(b*NHEAD + h)) * SEQ * DHEAD;

    // Q tiles (hi/lo) -> smem; query mask -> smem
    {
        const __nv_bfloat16* srch = qhi + hb + (size_t)q0 * DHEAD;
        const __nv_bfloat16* srcl = qlo + hb + (size_t)q0 * DHEAD;
        #pragma unroll
        for (int i = 0; i < 4; i++) {
            int lin = i*256 + tid;
            int r = lin >> 3, sgm = lin & 7;
            cp16(smem_u32(sm + S_QH + r*LQ + sgm*8), srch + r*DHEAD + sgm*8);
            cp16(smem_u32(sm + S_QL + r*LQ + sgm*8), srcl + r*DHEAD + sgm*8);
        }
        if (tid < 128) mqs[tid] = mask[b*SEQ + q0 + tid];
    }

    auto load_stage = [&](int t) {
        int st = t & 1;
        const size_t jb = hb + (size_t)t * 128 * DHEAD;
        __nv_bfloat16* dk = sm + S_STG + st * ASTG;
        #pragma unroll
        for (int i = 0; i < 4; i++) {
            int lin = i*256 + tid;
            int r = lin >> 3, sgm = lin & 7;
            int off = r*LQ + sgm*8;
            size_t go = (size_t)r*DHEAD + sgm*8;
            cp16(smem_u32(dk + off),            khi + jb + go);
            cp16(smem_u32(dk + 128*LQ + off),   klo + jb + go);
            cp16(smem_u32(dk + 2*128*LQ + off), vhi + jb + go);
            cp16(smem_u32(dk + 3*128*LQ + off), vlo + jb + go);
        }
        if (tid < 128) {
            float mv = mask[b*SEQ + t*128 + tid];
            madds[st*128 + tid] = (mv > 0.f) ? 0.f : -CUDART_INF_F;
        }
    };

    load_stage(0); cp_commit();
    load_stage(1); cp_commit();
    cp_wait<1>(); __syncthreads();

    // Q fragments -> registers (held for whole kernel)
    uint32_t aqh[4][4], aql[4][4];
    #pragma unroll
    for (int ks = 0; ks < 4; ks++) {
        int base = (w*16 + g)*LQ + ks*16 + tig*2;
        aqh[ks][0] = *(const uint32_t*)(sm + S_QH + base);
        aqh[ks][1] = *(const uint32_t*)(sm + S_QH + base + 8*LQ);
        aqh[ks][2] = *(const uint32_t*)(sm + S_QH + base + 8);
        aqh[ks][3] = *(const uint32_t*)(sm + S_QH + base + 8*LQ + 8);
        aql[ks][0] = *(const uint32_t*)(sm + S_QL + base);
        aql[ks][1] = *(const uint32_t*)(sm + S_QL + base + 8*LQ);
        aql[ks][2] = *(const uint32_t*)(sm + S_QL + base + 8);
        aql[ks][3] = *(const uint32_t*)(sm + S_QL + base + 8*LQ + 8);
    }

    float o[8][4];
    #pragma unroll
    for (int dt = 0; dt < 8; dt++)
        #pragma unroll
        for (int j = 0; j < 4; j++) o[dt][j] = 0.f;
    float m0 = -CUDART_INF_F, m1 = -CUDART_INF_F, l0 = 0.f, l1 = 0.f;

    #pragma unroll 1
    for (int t = 0; t < SEQ/128; t++) {
        const __nv_bfloat16* kh = sm + S_STG + (t & 1) * ASTG;
        const __nv_bfloat16* kl = kh + 128*LQ;
        const __nv_bfloat16* vh = kh + 2*128*LQ;
        const __nv_bfloat16* vl = kh + 3*128*LQ;
        const float* ma = madds + (t & 1) * 128;

        // ---- scores = Q K^T (3 split terms) ----
        float sc[16][4];
        #pragma unroll
        for (int nt = 0; nt < 16; nt++)
            #pragma unroll
            for (int j = 0; j < 4; j++) sc[nt][j] = 0.f;

        #pragma unroll
        for (int ks = 0; ks < 4; ks++) {
            #pragma unroll
            for (int nt = 0; nt < 16; nt++) {
                int nb = (nt*8 + g)*LQ + ks*16 + tig*2;
                uint32_t bh0 = *(const uint32_t*)(kh + nb);
                uint32_t bh1 = *(const uint32_t*)(kh + nb + 8);
                uint32_t bl0 = *(const uint32_t*)(kl + nb);
                uint32_t bl1 = *(const uint32_t*)(kl + nb + 8);
                mma_bf16a(sc[nt], aqh[ks], bh0, bh1);
                mma_bf16a(sc[nt], aqh[ks], bl0, bl1);
                mma_bf16a(sc[nt], aql[ks], bh0, bh1);
            }
        }

        // ---- masked online softmax (log2 domain) ----
        float nm0 = m0, nm1 = m1;
        #pragma unroll
        for (int nt = 0; nt < 16; nt++) {
            float2 mm = *(const float2*)(ma + nt*8 + tig*2);
            sc[nt][0] = fmaf(sc[nt][0], SCL2E, mm.x);
            sc[nt][1] = fmaf(sc[nt][1], SCL2E, mm.y);
            sc[nt][2] = fmaf(sc[nt][2], SCL2E, mm.x);
            sc[nt][3] = fmaf(sc[nt][3], SCL2E, mm.y);
            nm0 = fmaxf(nm0, fmaxf(sc[nt][0], sc[nt][1]));
            nm1 = fmaxf(nm1, fmaxf(sc[nt][2], sc[nt][3]));
        }
        nm0 = fmaxf(nm0, __shfl_xor_sync(0xffffffffu, nm0, 1));
        nm0 = fmaxf(nm0, __shfl_xor_sync(0xffffffffu, nm0, 2));
        nm1 = fmaxf(nm1, __shfl_xor_sync(0xffffffffu, nm1, 1));
        nm1 = fmaxf(nm1, __shfl_xor_sync(0xffffffffu, nm1, 2));
        float base0 = (nm0 == -CUDART_INF_F) ? 0.f : nm0;
        float base1 = (nm1 == -CUDART_INF_F) ? 0.f : nm1;
        float corr0 = ex2f(m0 - base0);
        float corr1 = ex2f(m1 - base1);

        float rs0 = 0.f, rs1 = 0.f;
        #pragma unroll
        for (int nt = 0; nt < 16; nt++) {
            sc[nt][0] = ex2f(sc[nt][0] - base0);
            sc[nt][1] = ex2f(sc[nt][1] - base0);
            sc[nt][2] = ex2f(sc[nt][2] - base1);
            sc[nt][3] = ex2f(sc[nt][3] - base1);
            rs0 += sc[nt][0] + sc[nt][1];
            rs1 += sc[nt][2] + sc[nt][3];
        }
        rs0 += __shfl_xor_sync(0xffffffffu, rs0, 1);
        rs0 += __shfl_xor_sync(0xffffffffu, rs0, 2);
        rs1 += __shfl_xor_sync(0xffffffffu, rs1, 1);
        rs1 += __shfl_xor_sync(0xffffffffu, rs1, 2);
        l0 = l0 * corr0 + rs0;
        l1 = l1 * corr1 + rs1;
        m0 = nm0; m1 = nm1;
        #pragma unroll
        for (int dt = 0; dt < 8; dt++) {
            o[dt][0] *= corr0; o[dt][1] *= corr0;
            o[dt][2] *= corr1; o[dt][3] *= corr1;
        }

        // ---- O += P V (3 split terms); P packed register-direct ----
        const int vro = (lane & 15)*LQ + ((lane >> 4) << 3);
        #pragma unroll
        for (int ks = 0; ks < 8; ks++) {
            uint32_t ah[4], al[4];
            pack_hilo(sc[2*ks][0],   sc[2*ks][1],   ah[0], al[0]);
            pack_hilo(sc[2*ks][2],   sc[2*ks][3],   ah[1], al[1]);
            pack_hilo(sc[2*ks+1][0], sc[2*ks+1][1], ah[2], al[2]);
            pack_hilo(sc[2*ks+1][2], sc[2*ks+1][3], ah[3], al[3]);
            const int vbase = ks*16*LQ + vro;
            #pragma unroll
            for (int ntp = 0; ntp < 4; ntp++) {
                uint32_t bh0, bh1, bh2, bh3, bl0, bl1, bl2, bl3;
                LDSM4T(bh0, bh1, bh2, bh3, smem_u32(vh + vbase + ntp*16));
                LDSM4T(bl0, bl1, bl2, bl3, smem_u32(vl + vbase + ntp*16));
                mma_bf16a(o[ntp*2],   ah, bh0, bh1);
                mma_bf16a(o[ntp*2],   ah, bl0, bl1);
                mma_bf16a(o[ntp*2],   al, bh0, bh1);
                mma_bf16a(o[ntp*2+1], ah, bh2, bh3);
                mma_bf16a(o[ntp*2+1], ah, bl2, bl3);
                mma_bf16a(o[ntp*2+1], al, bh2, bh3);
            }
        }

        __syncthreads();
        if (t + 2 < SEQ/128) {
            load_stage(t + 2); cp_commit(); cp_wait<1>();
        } else {
            cp_wait<0>();
        }
        __syncthreads();
    }

    // ---- finalize: /l, zero masked query rows ----
    float inv0 = (mqs[w*16 + g]     > 0.f && l0 > 0.f) ? (1.f / l0) : 0.f;
    float inv1 = (mqs[w*16 + g + 8] > 0.f && l1 > 0.f) ? (1.f / l1) : 0.f;
    int r0 = q0 + w*16 + g;
    float* out0 = xout + ((size_t)b*SEQ + r0)     * DMODEL + h*DHEAD;
    float* out1 = xout + ((size_t)b*SEQ + r0 + 8) * DMODEL + h*DHEAD;
    #pragma unroll
    for (int dt = 0; dt < 8; dt++) {
        *(float2*)(out0 + dt*8 + tig*2) = make_float2(o[dt][0]*inv0, o[dt][1]*inv0);
        *(float2*)(out1 + dt*8 + tig*2) = make_float2(o[dt][2]*inv1, o[dt][3]*inv1);
    }
}

// ---------------------------------------------------------------------------
extern "C" void kernel_launch(void* const* d_in, const int* in_sizes, int n_in,
                              void* d_out, int out_size)
{
    const float* X    = (const float*)d_in[0];
    const float* mask = (const float*)d_in[1];
    const float* Wq   = (const float*)d_in[2];
    const float* bq   = (const float*)d_in[3];
    const float* Wk   = (const float*)d_in[4];
    const float* bk   = (const float*)d_in[5];
    const float* Wv   = (const float*)d_in[6];
    const float* bv   = (const float*)d_in[7];
    const float* Wo   = (const float*)d_in[8];
    const float* bo   = (const float*)d_in[9];
    float* out = (float*)d_out;

    float *gx;
    cudaGetSymbolAddress((void**)&gx, g_x);

    __nv_bfloat16 *xhi, *xlo, *wqh, *wql, *wkh, *wkl, *wvh, *wvl, *woh, *wol, *gxh, *gxl;
    __nv_bfloat16 *qh, *ql, *kh, *kl, *vh, *vl;
    cudaGetSymbolAddress((void**)&xhi, g_xhi);
    cudaGetSymbolAddress((void**)&xlo, g_xlo);
    cudaGetSymbolAddress((void**)&wqh, g_wqhi);
    cudaGetSymbolAddress((void**)&wql, g_wqlo);
    cudaGetSymbolAddress((void**)&wkh, g_wkhi);
    cudaGetSymbolAddress((void**)&wkl, g_wklo);
    cudaGetSymbolAddress((void**)&wvh, g_wvhi);
    cudaGetSymbolAddress((void**)&wvl, g_wvlo);
    cudaGetSymbolAddress((void**)&woh, g_wohi);
    cudaGetSymbolAddress((void**)&wol, g_wolo);
    cudaGetSymbolAddress((void**)&gxh, g_gxhi);
    cudaGetSymbolAddress((void**)&gxl, g_gxlo);
    cudaGetSymbolAddress((void**)&qh, g_qhi);
    cudaGetSymbolAddress((void**)&ql, g_qlo);
    cudaGetSymbolAddress((void**)&kh, g_khi);
    cudaGetSymbolAddress((void**)&kl, g_klo);
    cudaGetSymbolAddress((void**)&vh, g_vhi);
    cudaGetSymbolAddress((void**)&vl, g_vlo);

    const int gemm_smem = 2 * STAGE_ELEMS * 2;          // 122880 B
    cudaFuncSetAttribute(mma_gemm<0>, cudaFuncAttributeMaxDynamicSharedMemorySize, gemm_smem);
    cudaFuncSetAttribute(mma_gemm<2>, cudaFuncAttributeMaxDynamicSharedMemorySize, gemm_smem);

    const int attn_smem = SM_BF16_ELEMS*2 + (256 + 128)*4;   // 185856 B
    cudaFuncSetAttribute(attn_mma_kernel, cudaFuncAttributeMaxDynamicSharedMemorySize, attn_smem);

    const int nX4 = BATCH*SEQ*DMODEL/4;
    const int nW4 = DMODEL*DMODEL/4;
    split_kernel<<<nX4/256, 256>>>(X,  xhi, xlo, nX4);
    split_kernel<<<nW4/256, 256>>>(Wq, wqh, wql, nW4);
    split_kernel<<<nW4/256, 256>>>(Wk, wkh, wkl, nW4);
    split_kernel<<<nW4/256, 256>>>(Wv, wvh, wvl, nW4);
    split_kernel<<<nW4/256, 256>>>(Wo, woh, wol, nW4);

    dim3 gg(DMODEL/256, (BATCH*SEQ)/128);   // (4, 32)
    mma_gemm<2><<<gg, 256, gemm_smem>>>(xhi, xlo, wqh, wql, bq, nullptr, qh, ql);
    mma_gemm<2><<<gg, 256, gemm_smem>>>(xhi, xlo, wkh, wkl, bk, nullptr, kh, kl);
    mma_gemm<2><<<gg, 256, gemm_smem>>>(xhi, xlo, wvh, wvl, bv, nullptr, vh, vl);

    dim3 gattn(SEQ/128, NHEAD, BATCH);      // (16, 16, 2)
    attn_mma_kernel<<<gattn, 256, attn_smem>>>(qh, ql, kh, kl, vh, vl, mask, gx);

    split_kernel<<<nX4/256, 256>>>(gx, gxh, gxl, nX4);
    mma_gemm<0><<<gg, 256, gemm_smem>>>(gxh, gxl, woh, wol, bo, out, nullptr, nullptr);
}

// round 13
// speedup vs baseline: 4.2887x; 1.4556x over previous
#include <cuda_runtime.h>
#include <cuda_fp16.h>
#include <math_constants.h>
#include <cstdint>

#define BATCH 2
#define SEQ   2048
#define DMODEL 1024
#define NHEAD 16
#define DHEAD 64

// ---------------------------------------------------------------------------
// Scratch (allocation-free device globals) — fp16 split planes
// ---------------------------------------------------------------------------
__device__ __half g_xhi[BATCH*SEQ*DMODEL];
__device__ __half g_xlo[BATCH*SEQ*DMODEL];
__device__ __half g_wq[DMODEL*DMODEL];     // hi-only weight planes
__device__ __half g_wk[DMODEL*DMODEL];
__device__ __half g_wv[DMODEL*DMODEL];
__device__ __half g_wo[DMODEL*DMODEL];

#define QKV_ELEMS (BATCH*NHEAD*SEQ*DHEAD)
__device__ __half g_qhi[QKV_ELEMS];
__device__ __half g_qlo[QKV_ELEMS];
__device__ __half g_khi[QKV_ELEMS];        // K,V need hi only
__device__ __half g_vhi[QKV_ELEMS];

__device__ __half g_gxhi[BATCH*SEQ*DMODEL];  // attn output, fp16 hi/lo
__device__ __half g_gxlo[BATCH*SEQ*DMODEL];

// ---------------------------------------------------------------------------
// Helpers
// ---------------------------------------------------------------------------
__device__ __forceinline__ uint32_t smem_u32(const void* p) {
    uint32_t a;
    asm("{ .reg .u64 t; cvta.to.shared.u64 t, %1; cvt.u32.u64 %0, t; }"
        : "=r"(a) : "l"(p));
    return a;
}
__device__ __forceinline__ void cp16(uint32_t dst, const void* src) {
    asm volatile("cp.async.cg.shared.global [%0], [%1], 16;"
                 :: "r"(dst), "l"(src) : "memory");
}
__device__ __forceinline__ void cp_commit() {
    asm volatile("cp.async.commit_group;" ::: "memory");
}
template<int N>
__device__ __forceinline__ void cp_wait() {
    asm volatile("cp.async.wait_group %0;" :: "n"(N) : "memory");
}
__device__ __forceinline__ void mma_f16(float c[4], uint32_t a0, uint32_t a1,
                                        uint32_t a2, uint32_t a3,
                                        uint32_t b0, uint32_t b1) {
    asm volatile(
        "mma.sync.aligned.m16n8k16.row.col.f32.f16.f16.f32 "
        "{%0,%1,%2,%3}, {%4,%5,%6,%7}, {%8,%9}, {%0,%1,%2,%3};"
        : "+f"(c[0]), "+f"(c[1]), "+f"(c[2]), "+f"(c[3])
        : "r"(a0), "r"(a1), "r"(a2), "r"(a3), "r"(b0), "r"(b1));
}
__device__ __forceinline__ void mma_f16a(float c[4], const uint32_t a[4],
                                         uint32_t b0, uint32_t b1) {
    mma_f16(c, a[0], a[1], a[2], a[3], b0, b1);
}
#define LDSM4T(r0,r1,r2,r3,addr) \
    asm volatile("ldmatrix.sync.aligned.m8n8.x4.trans.shared.b16 {%0,%1,%2,%3}, [%4];" \
        : "=r"(r0),"=r"(r1),"=r"(r2),"=r"(r3) : "r"(addr))

__device__ __forceinline__ float ex2f(float x) {
    float r; asm("ex2.approx.f32 %0, %1;" : "=f"(r) : "f"(x)); return r;
}
__device__ __forceinline__ uint32_t pack_f16x2(float x, float y) {
    uint32_t r;  // x -> low half, y -> high half
    asm("cvt.rn.f16x2.f32 %0, %1, %2;" : "=r"(r) : "f"(y), "f"(x));
    return r;
}
__device__ __forceinline__ void pack_hilo(float x, float y,
                                          uint32_t& hi, uint32_t& lo) {
    hi = pack_f16x2(x, y);
    __half2 h2 = *reinterpret_cast<__half2*>(&hi);
    lo = pack_f16x2(x - __half2float(h2.x), y - __half2float(h2.y));
}

// ---------------------------------------------------------------------------
// Split kernels: fp32 -> fp16 hi (+ lo residual)
// ---------------------------------------------------------------------------
__global__ void __launch_bounds__(256) split2_kernel(
    const float* __restrict__ src, __half* __restrict__ hi,
    __half* __restrict__ lo, int n4)
{
    int i = blockIdx.x * blockDim.x + threadIdx.x;
    if (i >= n4) return;
    float4 v = ((const float4*)src)[i];
    float vv[4] = {v.x, v.y, v.z, v.w};
    #pragma unroll
    for (int j = 0; j < 4; j++) {
        __half h = __float2half_rn(vv[j]);
        hi[i*4 + j] = h;
        lo[i*4 + j] = __float2half_rn(vv[j] - __half2float(h));
    }
}
__global__ void __launch_bounds__(256) split1_kernel(
    const float* __restrict__ src, __half* __restrict__ hi, int n4)
{
    int i = blockIdx.x * blockDim.x + threadIdx.x;
    if (i >= n4) return;
    float4 v = ((const float4*)src)[i];
    __half2* h2 = (__half2*)(hi + i*4);
    h2[0] = __floats2half2_rn(v.x, v.y);
    h2[1] = __floats2half2_rn(v.z, v.w);
}

// ---------------------------------------------------------------------------
// fp16 2-term HMMA GEMM core: C = (A_hi + A_lo) @ B_hi^T  (fp32 accum)
// CTA tile 128x256, 8 warps 64x64, K chunks 32, double-buffered cp.async.
// ---------------------------------------------------------------------------
#define LDK 40
#define ST_AHI 0
#define ST_ALO (128*LDK)
#define ST_BHI (2*128*LDK)
#define STAGE_ELEMS (2*128*LDK + 256*LDK)   // 20480 halves = 40960 B

__device__ __forceinline__ void gemm_load_stage(
    __half* sb, int st,
    const __half* __restrict__ Ahi, const __half* __restrict__ Alo,
    const __half* __restrict__ Bh, int m0, int n0, int k0, int tid)
{
    __half* s = sb + st * STAGE_ELEMS;
    #pragma unroll
    for (int i = 0; i < 2; i++) {
        int lin = i * 256 + tid;
        int r = lin >> 2, seg = lin & 3;
        cp16(smem_u32(s + ST_AHI + r * LDK + seg * 8),
             Ahi + (size_t)(m0 + r) * DMODEL + k0 + seg * 8);
        cp16(smem_u32(s + ST_ALO + r * LDK + seg * 8),
             Alo + (size_t)(m0 + r) * DMODEL + k0 + seg * 8);
    }
    #pragma unroll
    for (int i = 0; i < 4; i++) {
        int lin = i * 256 + tid;
        int r = lin >> 2, seg = lin & 3;
        cp16(smem_u32(s + ST_BHI + r * LDK + seg * 8),
             Bh + (size_t)(n0 + r) * DMODEL + k0 + seg * 8);
    }
}

__device__ __forceinline__ void gemm2_core(
    __half* sb, const __half* __restrict__ Ahi, const __half* __restrict__ Alo,
    const __half* __restrict__ Bh, int m0, int n0, int tid,
    float (&acc)[4][8][4])
{
    const int lane = tid & 31;
    const int g    = lane >> 2;
    const int tig  = lane & 3;
    const int wm = (tid >> 5) & 1;
    const int wn = (tid >> 5) >> 1;

    gemm_load_stage(sb, 0, Ahi, Alo, Bh, m0, n0, 0, tid);
    cp_commit();

    const int NC = DMODEL / 32;
    #pragma unroll 1
    for (int c = 0; c < NC; c++) {
        if (c + 1 < NC) {
            gemm_load_stage(sb, (c + 1) & 1, Ahi, Alo, Bh, m0, n0, (c + 1) * 32, tid);
            cp_commit();
            cp_wait<1>();
        } else {
            cp_wait<0>();
        }
        __syncthreads();

        const __half* s   = sb + (c & 1) * STAGE_ELEMS;
        const __half* sAh = s + ST_AHI;
        const __half* sAl = s + ST_ALO;
        const __half* sB  = s + ST_BHI;

        #pragma unroll
        for (int sstep = 0; sstep < 2; sstep++) {
            const int koff = sstep * 16;
            uint32_t a[4][4], al[4][4], b[8][2];
            #pragma unroll
            for (int mt = 0; mt < 4; mt++) {
                int base = (wm*64 + mt*16 + g) * LDK + koff + tig*2;
                a[mt][0]  = *(const uint32_t*)(sAh + base);
                a[mt][1]  = *(const uint32_t*)(sAh + base + 8*LDK);
                a[mt][2]  = *(const uint32_t*)(sAh + base + 8);
                a[mt][3]  = *(const uint32_t*)(sAh + base + 8*LDK + 8);
                al[mt][0] = *(const uint32_t*)(sAl + base);
                al[mt][1] = *(const uint32_t*)(sAl + base + 8*LDK);
                al[mt][2] = *(const uint32_t*)(sAl + base + 8);
                al[mt][3] = *(const uint32_t*)(sAl + base + 8*LDK + 8);
            }
            #pragma unroll
            for (int nt = 0; nt < 8; nt++) {
                int nb = (wn*64 + nt*8 + g) * LDK + koff + tig*2;
                b[nt][0] = *(const uint32_t*)(sB + nb);
                b[nt][1] = *(const uint32_t*)(sB + nb + 8);
            }
            #pragma unroll
            for (int mt = 0; mt < 4; mt++)
                #pragma unroll
                for (int nt = 0; nt < 8; nt++)
                    mma_f16a(acc[mt][nt], a[mt], b[nt][0], b[nt][1]);
            #pragma unroll
            for (int mt = 0; mt < 4; mt++)
                #pragma unroll
                for (int nt = 0; nt < 8; nt++)
                    mma_f16a(acc[mt][nt], al[mt], b[nt][0], b[nt][1]);
        }
        __syncthreads();
    }
}

// QKV fused GEMM: blockIdx.z selects {Wq->Q(hi,lo), Wk->K(hi), Wv->V(hi)}
__global__ void __launch_bounds__(256, 1) qkv_gemm(
    const __half* __restrict__ xhi, const __half* __restrict__ xlo,
    const __half* __restrict__ wq, const __half* __restrict__ wk,
    const __half* __restrict__ wv,
    const float* __restrict__ bq, const float* __restrict__ bk,
    const float* __restrict__ bv,
    __half* __restrict__ qh, __half* __restrict__ ql,
    __half* __restrict__ kh, __half* __restrict__ vh)
{
    extern __shared__ __align__(16) __half sb[];
    const int z = blockIdx.z;
    const __half* W     = (z == 0) ? wq : (z == 1) ? wk : wv;
    const float*  bias  = (z == 0) ? bq : (z == 1) ? bk : bv;
    __half* oh          = (z == 0) ? qh : (z == 1) ? kh : vh;
    __half* ol          = (z == 0) ? ql : nullptr;

    const int tid = threadIdx.x;
    const int m0 = blockIdx.y * 128;
    const int n0 = blockIdx.x * 256;

    float acc[4][8][4];
    #pragma unroll
    for (int mt = 0; mt < 4; mt++)
        #pragma unroll
        for (int nt = 0; nt < 8; nt++)
            #pragma unroll
            for (int r = 0; r < 4; r++) acc[mt][nt][r] = 0.f;

    gemm2_core(sb, xhi, xlo, W, m0, n0, tid, acc);

    const int lane = tid & 31, g = lane >> 2, tig = lane & 3;
    const int wm = (tid >> 5) & 1, wn = (tid >> 5) >> 1;
    #pragma unroll
    for (int mt = 0; mt < 4; mt++) {
        #pragma unroll
        for (int nt = 0; nt < 8; nt++) {
            int col = n0 + wn*64 + nt*8 + tig*2;
            float2 bb = *(const float2*)(bias + col);
            int row = m0 + wm*64 + mt*16 + g;
            float o0x = acc[mt][nt][0] + bb.x, o0y = acc[mt][nt][1] + bb.y;
            float o1x = acc[mt][nt][2] + bb.x, o1y = acc[mt][nt][3] + bb.y;
            int h = col >> 6, dh = col & 63;
            int b0i = row >> 11, s0 = row & (SEQ - 1);
            int b1i = (row + 8) >> 11, s1 = (row + 8) & (SEQ - 1);
            size_t i0 = ((size_t)(b0i*NHEAD + h)*SEQ + s0)*DHEAD + dh;
            size_t i1 = ((size_t)(b1i*NHEAD + h)*SEQ + s1)*DHEAD + dh;
            uint32_t phi, plo;
            if (ol) {
                pack_hilo(o0x, o0y, phi, plo);
                *(uint32_t*)(oh + i0) = phi;
                *(uint32_t*)(ol + i0) = plo;
                pack_hilo(o1x, o1y, phi, plo);
                *(uint32_t*)(oh + i1) = phi;
                *(uint32_t*)(ol + i1) = plo;
            } else {
                *(uint32_t*)(oh + i0) = pack_f16x2(o0x, o0y);
                *(uint32_t*)(oh + i1) = pack_f16x2(o1x, o1y);
            }
        }
    }
}

// Output GEMM: fp32 row-major out = (gxh+gxl) @ Wo^T + bo
__global__ void __launch_bounds__(256, 1) out_gemm(
    const __half* __restrict__ Ahi, const __half* __restrict__ Alo,
    const __half* __restrict__ Bh, const float* __restrict__ bias,
    float* __restrict__ C)
{
    extern __shared__ __align__(16) __half sb[];
    const int tid = threadIdx.x;
    const int m0 = blockIdx.y * 128;
    const int n0 = blockIdx.x * 256;

    float acc[4][8][4];
    #pragma unroll
    for (int mt = 0; mt < 4; mt++)
        #pragma unroll
        for (int nt = 0; nt < 8; nt++)
            #pragma unroll
            for (int r = 0; r < 4; r++) acc[mt][nt][r] = 0.f;

    gemm2_core(sb, Ahi, Alo, Bh, m0, n0, tid, acc);

    const int lane = tid & 31, g = lane >> 2, tig = lane & 3;
    const int wm = (tid >> 5) & 1, wn = (tid >> 5) >> 1;
    #pragma unroll
    for (int mt = 0; mt < 4; mt++) {
        #pragma unroll
        for (int nt = 0; nt < 8; nt++) {
            int col = n0 + wn*64 + nt*8 + tig*2;
            float2 bb = *(const float2*)(bias + col);
            int row = m0 + wm*64 + mt*16 + g;
            *(float2*)(C + (size_t)row * DMODEL + col) =
                make_float2(acc[mt][nt][0] + bb.x, acc[mt][nt][1] + bb.y);
            *(float2*)(C + (size_t)(row + 8) * DMODEL + col) =
                make_float2(acc[mt][nt][2] + bb.x, acc[mt][nt][3] + bb.y);
        }
    }
}

// ---------------------------------------------------------------------------
// fp16 2-term HMMA flash attention.
// Grid (S/128, H, B), 256 thr = 8 warps x 16 q-rows. Log2-domain softmax,
// additive 0/-inf mask. Output written as fp16 hi/lo planes.
// ---------------------------------------------------------------------------
#define LQ 72
#define S_QH 0
#define S_QL (128*LQ)
#define S_STG (2*128*LQ)
#define ASTG  (2*128*LQ)                 // per stage: K_hi + V_hi
#define SM_HALF_ELEMS (S_STG + 2*ASTG)   // 55296
#define SCL2E 0.1803368801111244f        // 0.125 * log2(e)

__global__ void __launch_bounds__(256, 1) attn_mma_kernel(
    const __half* __restrict__ qhi, const __half* __restrict__ qlo,
    const __half* __restrict__ khi, const __half* __restrict__ vhi,
    const float* __restrict__ mask,
    __half* __restrict__ xh, __half* __restrict__ xl)
{
    extern __shared__ __align__(16) __half sm[];
    float* fsec  = (float*)(sm + SM_HALF_ELEMS);
    float* madds = fsec;          // [2][128]
    float* mqs   = fsec + 256;    // [128]

    const int tid  = threadIdx.x;
    const int w    = tid >> 5;
    const int lane = tid & 31;
    const int g    = lane >> 2;
    const int tig  = lane & 3;
    const int q0 = blockIdx.x * 128;
    const int h  = blockIdx.y;
    const int b  = blockIdx.z;
    const size_t hb = ((size_t)(b*NHEAD + h)) * SEQ * DHEAD;

    {
        const __half* srch = qhi + hb + (size_t)q0 * DHEAD;
        const __half* srcl = qlo + hb + (size_t)q0 * DHEAD;
        #pragma unroll
        for (int i = 0; i < 4; i++) {
            int lin = i*256 + tid;
            int r = lin >> 3, sgm = lin & 7;
            cp16(smem_u32(sm + S_QH + r*LQ + sgm*8), srch + r*DHEAD + sgm*8);
            cp16(smem_u32(sm + S_QL + r*LQ + sgm*8), srcl + r*DHEAD + sgm*8);
        }
        if (tid < 128) mqs[tid] = mask[b*SEQ + q0 + tid];
    }

    auto load_stage = [&](int t) {
        int st = t & 1;
        const size_t jb = hb + (size_t)t * 128 * DHEAD;
        __half* dk = sm + S_STG + st * ASTG;
        #pragma unroll
        for (int i = 0; i < 4; i++) {
            int lin = i*256 + tid;
            int r = lin >> 3, sgm = lin & 7;
            int off = r*LQ + sgm*8;
            size_t go = (size_t)r*DHEAD + sgm*8;
            cp16(smem_u32(dk + off),          khi + jb + go);
            cp16(smem_u32(dk + 128*LQ + off), vhi + jb + go);
        }
        if (tid < 128) {
            float mv = mask[b*SEQ + t*128 + tid];
            madds[st*128 + tid] = (mv > 0.f) ? 0.f : -CUDART_INF_F;
        }
    };

    load_stage(0); cp_commit();
    load_stage(1); cp_commit();
    cp_wait<1>(); __syncthreads();

    uint32_t aqh[4][4], aql[4][4];
    #pragma unroll
    for (int ks = 0; ks < 4; ks++) {
        int base = (w*16 + g)*LQ + ks*16 + tig*2;
        aqh[ks][0] = *(const uint32_t*)(sm + S_QH + base);
        aqh[ks][1] = *(const uint32_t*)(sm + S_QH + base + 8*LQ);
        aqh[ks][2] = *(const uint32_t*)(sm + S_QH + base + 8);
        aqh[ks][3] = *(const uint32_t*)(sm + S_QH + base + 8*LQ + 8);
        aql[ks][0] = *(const uint32_t*)(sm + S_QL + base);
        aql[ks][1] = *(const uint32_t*)(sm + S_QL + base + 8*LQ);
        aql[ks][2] = *(const uint32_t*)(sm + S_QL + base + 8);
        aql[ks][3] = *(const uint32_t*)(sm + S_QL + base + 8*LQ + 8);
    }

    float o[8][4];
    #pragma unroll
    for (int dt = 0; dt < 8; dt++)
        #pragma unroll
        for (int j = 0; j < 4; j++) o[dt][j] = 0.f;
    float m0 = -CUDART_INF_F, m1 = -CUDART_INF_F, l0 = 0.f, l1 = 0.f;

    #pragma unroll 1
    for (int t = 0; t < SEQ/128; t++) {
        const __half* kh = sm + S_STG + (t & 1) * ASTG;
        const __half* vh = kh + 128*LQ;
        const float* ma = madds + (t & 1) * 128;

        // ---- scores = Q K^T (2 split terms) ----
        float sc[16][4];
        #pragma unroll
        for (int nt = 0; nt < 16; nt++)
            #pragma unroll
            for (int j = 0; j < 4; j++) sc[nt][j] = 0.f;

        #pragma unroll
        for (int ks = 0; ks < 4; ks++) {
            #pragma unroll
            for (int nt = 0; nt < 16; nt++) {
                int nb = (nt*8 + g)*LQ + ks*16 + tig*2;
                uint32_t bh0 = *(const uint32_t*)(kh + nb);
                uint32_t bh1 = *(const uint32_t*)(kh + nb + 8);
                mma_f16a(sc[nt], aqh[ks], bh0, bh1);
                mma_f16a(sc[nt], aql[ks], bh0, bh1);
            }
        }

        // ---- masked online softmax (log2 domain) ----
        float nm0 = m0, nm1 = m1;
        #pragma unroll
        for (int nt = 0; nt < 16; nt++) {
            float2 mm = *(const float2*)(ma + nt*8 + tig*2);
            sc[nt][0] = fmaf(sc[nt][0], SCL2E, mm.x);
            sc[nt][1] = fmaf(sc[nt][1], SCL2E, mm.y);
            sc[nt][2] = fmaf(sc[nt][2], SCL2E, mm.x);
            sc[nt][3] = fmaf(sc[nt][3], SCL2E, mm.y);
            nm0 = fmaxf(nm0, fmaxf(sc[nt][0], sc[nt][1]));
            nm1 = fmaxf(nm1, fmaxf(sc[nt][2], sc[nt][3]));
        }
        nm0 = fmaxf(nm0, __shfl_xor_sync(0xffffffffu, nm0, 1));
        nm0 = fmaxf(nm0, __shfl_xor_sync(0xffffffffu, nm0, 2));
        nm1 = fmaxf(nm1, __shfl_xor_sync(0xffffffffu, nm1, 1));
        nm1 = fmaxf(nm1, __shfl_xor_sync(0xffffffffu, nm1, 2));
        float base0 = (nm0 == -CUDART_INF_F) ? 0.f : nm0;
        float base1 = (nm1 == -CUDART_INF_F) ? 0.f : nm1;
        float corr0 = ex2f(m0 - base0);
        float corr1 = ex2f(m1 - base1);

        float rs0 = 0.f, rs1 = 0.f;
        #pragma unroll
        for (int nt = 0; nt < 16; nt++) {
            sc[nt][0] = ex2f(sc[nt][0] - base0);
            sc[nt][1] = ex2f(sc[nt][1] - base0);
            sc[nt][2] = ex2f(sc[nt][2] - base1);
            sc[nt][3] = ex2f(sc[nt][3] - base1);
            rs0 += sc[nt][0] + sc[nt][1];
            rs1 += sc[nt][2] + sc[nt][3];
        }
        rs0 += __shfl_xor_sync(0xffffffffu, rs0, 1);
        rs0 += __shfl_xor_sync(0xffffffffu, rs0, 2);
        rs1 += __shfl_xor_sync(0xffffffffu, rs1, 1);
        rs1 += __shfl_xor_sync(0xffffffffu, rs1, 2);
        l0 = l0 * corr0 + rs0;
        l1 = l1 * corr1 + rs1;
        m0 = nm0; m1 = nm1;
        #pragma unroll
        for (int dt = 0; dt < 8; dt++) {
            o[dt][0] *= corr0; o[dt][1] *= corr0;
            o[dt][2] *= corr1; o[dt][3] *= corr1;
        }

        // ---- O += P V (2 split terms); P packed register-direct ----
        const int vro = (lane & 15)*LQ + ((lane >> 4) << 3);
        #pragma unroll
        for (int ks = 0; ks < 8; ks++) {
            uint32_t ah[4], al[4];
            pack_hilo(sc[2*ks][0],   sc[2*ks][1],   ah[0], al[0]);
            pack_hilo(sc[2*ks][2],   sc[2*ks][3],   ah[1], al[1]);
            pack_hilo(sc[2*ks+1][0], sc[2*ks+1][1], ah[2], al[2]);
            pack_hilo(sc[2*ks+1][2], sc[2*ks+1][3], ah[3], al[3]);
            const int vbase = ks*16*LQ + vro;
            #pragma unroll
            for (int ntp = 0; ntp < 4; ntp++) {
                uint32_t bh0, bh1, bh2, bh3;
                LDSM4T(bh0, bh1, bh2, bh3, smem_u32(vh + vbase + ntp*16));
                mma_f16a(o[ntp*2],   ah, bh0, bh1);
                mma_f16a(o[ntp*2],   al, bh0, bh1);
                mma_f16a(o[ntp*2+1], ah, bh2, bh3);
                mma_f16a(o[ntp*2+1], al, bh2, bh3);
            }
        }

        __syncthreads();
        if (t + 2 < SEQ/128) {
            load_stage(t + 2); cp_commit(); cp_wait<1>();
        } else {
            cp_wait<0>();
        }
        __syncthreads();
    }

    // ---- finalize: /l, zero masked query rows, write fp16 hi/lo ----
    float inv0 = (mqs[w*16 + g]     > 0.f && l0 > 0.f) ? (1.f / l0) : 0.f;
    float inv1 = (mqs[w*16 + g + 8] > 0.f && l1 > 0.f) ? (1.f / l1) : 0.f;
    int r0 = q0 + w*16 + g;
    size_t o0b = ((size_t)b*SEQ + r0)     * DMODEL + h*DHEAD;
    size_t o1b = ((size_t)b*SEQ + r0 + 8) * DMODEL + h*DHEAD;
    #pragma unroll
    for (int dt = 0; dt < 8; dt++) {
        uint32_t phi, plo;
        pack_hilo(o[dt][0]*inv0, o[dt][1]*inv0, phi, plo);
        *(uint32_t*)(xh + o0b + dt*8 + tig*2) = phi;
        *(uint32_t*)(xl + o0b + dt*8 + tig*2) = plo;
        pack_hilo(o[dt][2]*inv1, o[dt][3]*inv1, phi, plo);
        *(uint32_t*)(xh + o1b + dt*8 + tig*2) = phi;
        *(uint32_t*)(xl + o1b + dt*8 + tig*2) = plo;
    }
}

// ---------------------------------------------------------------------------
extern "C" void kernel_launch(void* const* d_in, const int* in_sizes, int n_in,
                              void* d_out, int out_size)
{
    const float* X    = (const float*)d_in[0];
    const float* mask = (const float*)d_in[1];
    const float* Wq   = (const float*)d_in[2];
    const float* bq   = (const float*)d_in[3];
    const float* Wk   = (const float*)d_in[4];
    const float* bk   = (const float*)d_in[5];
    const float* Wv   = (const float*)d_in[6];
    const float* bv   = (const float*)d_in[7];
    const float* Wo   = (const float*)d_in[8];
    const float* bo   = (const float*)d_in[9];
    float* out = (float*)d_out;

    __half *xhi, *xlo, *wq, *wk, *wv, *wo, *qh, *ql, *kh, *vh, *gxh, *gxl;
    cudaGetSymbolAddress((void**)&xhi, g_xhi);
    cudaGetSymbolAddress((void**)&xlo, g_xlo);
    cudaGetSymbolAddress((void**)&wq,  g_wq);
    cudaGetSymbolAddress((void**)&wk,  g_wk);
    cudaGetSymbolAddress((void**)&wv,  g_wv);
    cudaGetSymbolAddress((void**)&wo,  g_wo);
    cudaGetSymbolAddress((void**)&qh,  g_qhi);
    cudaGetSymbolAddress((void**)&ql,  g_qlo);
    cudaGetSymbolAddress((void**)&kh,  g_khi);
    cudaGetSymbolAddress((void**)&vh,  g_vhi);
    cudaGetSymbolAddress((void**)&gxh, g_gxhi);
    cudaGetSymbolAddress((void**)&gxl, g_gxlo);

    const int gemm_smem = 2 * STAGE_ELEMS * 2;   // 81920 B
    cudaFuncSetAttribute(qkv_gemm, cudaFuncAttributeMaxDynamicSharedMemorySize, gemm_smem);
    cudaFuncSetAttribute(out_gemm, cudaFuncAttributeMaxDynamicSharedMemorySize, gemm_smem);

    const int attn_smem = SM_HALF_ELEMS*2 + (256 + 128)*4;   // 112128 B
    cudaFuncSetAttribute(attn_mma_kernel, cudaFuncAttributeMaxDynamicSharedMemorySize, attn_smem);

    const int nX4 = BATCH*SEQ*DMODEL/4;
    const int nW4 = DMODEL*DMODEL/4;
    split2_kernel<<<nX4/256, 256>>>(X,  xhi, xlo, nX4);
    split1_kernel<<<nW4/256, 256>>>(Wq, wq, nW4);
    split1_kernel<<<nW4/256, 256>>>(Wk, wk, nW4);
    split1_kernel<<<nW4/256, 256>>>(Wv, wv, nW4);
    split1_kernel<<<nW4/256, 256>>>(Wo, wo, nW4);

    dim3 gqkv(DMODEL/256, (BATCH*SEQ)/128, 3);   // (4, 32, 3)
    qkv_gemm<<<gqkv, 256, gemm_smem>>>(xhi, xlo, wq, wk, wv, bq, bk, bv,
                                       qh, ql, kh, vh);

    dim3 gattn(SEQ/128, NHEAD, BATCH);           // (16, 16, 2)
    attn_mma_kernel<<<gattn, 256, attn_smem>>>(qh, ql, kh, vh, mask, gxh, gxl);

    dim3 gout(DMODEL/256, (BATCH*SEQ)/128);      // (4, 32)
    out_gemm<<<gout, 256, gemm_smem>>>(gxh, gxl, wo, bo, out);
}

// round 15
// speedup vs baseline: 6.6946x; 1.5610x over previous
#include <cuda_runtime.h>
#include <cuda_fp16.h>
#include <math_constants.h>
#include <cstdint>

#define BATCH 2
#define SEQ   2048
#define DMODEL 1024
#define NHEAD 16
#define DHEAD 64

// ---------------------------------------------------------------------------
// Scratch (allocation-free device globals) — single fp16 planes
// ---------------------------------------------------------------------------
__device__ __half g_xh[BATCH*SEQ*DMODEL];
__device__ __half g_wq[DMODEL*DMODEL];
__device__ __half g_wk[DMODEL*DMODEL];
__device__ __half g_wv[DMODEL*DMODEL];
__device__ __half g_wo[DMODEL*DMODEL];

#define QKV_ELEMS (BATCH*NHEAD*SEQ*DHEAD)
__device__ __half g_qh[QKV_ELEMS];
__device__ __half g_kh[QKV_ELEMS];
__device__ __half g_vh[QKV_ELEMS];

__device__ __half g_gxh[BATCH*SEQ*DMODEL];   // attn output (fp16)

// ---------------------------------------------------------------------------
// Helpers
// ---------------------------------------------------------------------------
__device__ __forceinline__ uint32_t smem_u32(const void* p) {
    uint32_t a;
    asm("{ .reg .u64 t; cvta.to.shared.u64 t, %1; cvt.u32.u64 %0, t; }"
        : "=r"(a) : "l"(p));
    return a;
}
__device__ __forceinline__ void cp16(uint32_t dst, const void* src) {
    asm volatile("cp.async.cg.shared.global [%0], [%1], 16;"
                 :: "r"(dst), "l"(src) : "memory");
}
__device__ __forceinline__ void cp_commit() {
    asm volatile("cp.async.commit_group;" ::: "memory");
}
template<int N>
__device__ __forceinline__ void cp_wait() {
    asm volatile("cp.async.wait_group %0;" :: "n"(N) : "memory");
}
__device__ __forceinline__ void mma_f16(float c[4], uint32_t a0, uint32_t a1,
                                        uint32_t a2, uint32_t a3,
                                        uint32_t b0, uint32_t b1) {
    asm volatile(
        "mma.sync.aligned.m16n8k16.row.col.f32.f16.f16.f32 "
        "{%0,%1,%2,%3}, {%4,%5,%6,%7}, {%8,%9}, {%0,%1,%2,%3};"
        : "+f"(c[0]), "+f"(c[1]), "+f"(c[2]), "+f"(c[3])
        : "r"(a0), "r"(a1), "r"(a2), "r"(a3), "r"(b0), "r"(b1));
}
__device__ __forceinline__ void mma_f16a(float c[4], const uint32_t a[4],
                                         uint32_t b0, uint32_t b1) {
    mma_f16(c, a[0], a[1], a[2], a[3], b0, b1);
}
#define LDSM4T(r0,r1,r2,r3,addr) \
    asm volatile("ldmatrix.sync.aligned.m8n8.x4.trans.shared.b16 {%0,%1,%2,%3}, [%4];" \
        : "=r"(r0),"=r"(r1),"=r"(r2),"=r"(r3) : "r"(addr))

__device__ __forceinline__ float ex2f(float x) {
    float r; asm("ex2.approx.f32 %0, %1;" : "=f"(r) : "f"(x)); return r;
}
__device__ __forceinline__ uint32_t pack_f16x2(float x, float y) {
    uint32_t r;  // x -> low half, y -> high half
    asm("cvt.rn.f16x2.f32 %0, %1, %2;" : "=r"(r) : "f"(y), "f"(x));
    return r;
}

// ---------------------------------------------------------------------------
// Fused split: fp32 -> fp16 for X + all four weight matrices (one launch)
// ---------------------------------------------------------------------------
#define NX4 (BATCH*SEQ*DMODEL/4)    // 1048576 float4s
#define NW4 (DMODEL*DMODEL/4)       // 262144 float4s

__global__ void __launch_bounds__(256) split_all_kernel(
    const float* __restrict__ X,  const float* __restrict__ Wq,
    const float* __restrict__ Wk, const float* __restrict__ Wv,
    const float* __restrict__ Wo,
    __half* __restrict__ xh, __half* __restrict__ wq, __half* __restrict__ wk,
    __half* __restrict__ wv, __half* __restrict__ wo)
{
    int i = blockIdx.x * blockDim.x + threadIdx.x;
    const float* src; __half* dst; int off;
    if (i < NX4) {
        src = X; dst = xh; off = i;
    } else {
        int j = i - NX4;
        int w = j >> 18;               // j / NW4
        off = j & (NW4 - 1);
        src = (w == 0) ? Wq : (w == 1) ? Wk : (w == 2) ? Wv : Wo;
        dst = (w == 0) ? wq : (w == 1) ? wk : (w == 2) ? wv : wo;
    }
    float4 v = ((const float4*)src)[off];
    __half2* h2 = (__half2*)(dst + (size_t)off * 4);
    h2[0] = __floats2half2_rn(v.x, v.y);
    h2[1] = __floats2half2_rn(v.z, v.w);
}

// ---------------------------------------------------------------------------
// fp16 HMMA GEMM core: C = A @ B^T (fp32 accum), 1-term.
// CTA tile 128x256, 8 warps 64x64, K chunks 32, double-buffered cp.async.
// ---------------------------------------------------------------------------
#define LDK 40
#define ST_A 0
#define ST_B (128*LDK)
#define STAGE_ELEMS (128*LDK + 256*LDK)   // 15360 halves = 30720 B

__device__ __forceinline__ void gemm_load_stage(
    __half* sb, int st, const __half* __restrict__ A,
    const __half* __restrict__ B, int m0, int n0, int k0, int tid)
{
    __half* s = sb + st * STAGE_ELEMS;
    #pragma unroll
    for (int i = 0; i < 2; i++) {
        int lin = i * 256 + tid;
        int r = lin >> 2, seg = lin & 3;
        cp16(smem_u32(s + ST_A + r * LDK + seg * 8),
             A + (size_t)(m0 + r) * DMODEL + k0 + seg * 8);
    }
    #pragma unroll
    for (int i = 0; i < 4; i++) {
        int lin = i * 256 + tid;
        int r = lin >> 2, seg = lin & 3;
        cp16(smem_u32(s + ST_B + r * LDK + seg * 8),
             B + (size_t)(n0 + r) * DMODEL + k0 + seg * 8);
    }
}

__device__ __forceinline__ void gemm_core(
    __half* sb, const __half* __restrict__ A, const __half* __restrict__ B,
    int m0, int n0, int tid, float (&acc)[4][8][4])
{
    const int lane = tid & 31;
    const int g    = lane >> 2;
    const int tig  = lane & 3;
    const int wm = (tid >> 5) & 1;
    const int wn = (tid >> 5) >> 1;

    gemm_load_stage(sb, 0, A, B, m0, n0, 0, tid);
    cp_commit();

    const int NC = DMODEL / 32;
    #pragma unroll 1
    for (int c = 0; c < NC; c++) {
        if (c + 1 < NC) {
            gemm_load_stage(sb, (c + 1) & 1, A, B, m0, n0, (c + 1) * 32, tid);
            cp_commit();
            cp_wait<1>();
        } else {
            cp_wait<0>();
        }
        __syncthreads();

        const __half* s  = sb + (c & 1) * STAGE_ELEMS;
        const __half* sA = s + ST_A;
        const __half* sB = s + ST_B;

        #pragma unroll
        for (int sstep = 0; sstep < 2; sstep++) {
            const int koff = sstep * 16;
            uint32_t a[4][4], b[8][2];
            #pragma unroll
            for (int mt = 0; mt < 4; mt++) {
                int base = (wm*64 + mt*16 + g) * LDK + koff + tig*2;
                a[mt][0] = *(const uint32_t*)(sA + base);
                a[mt][1] = *(const uint32_t*)(sA + base + 8*LDK);
                a[mt][2] = *(const uint32_t*)(sA + base + 8);
                a[mt][3] = *(const uint32_t*)(sA + base + 8*LDK + 8);
            }
            #pragma unroll
            for (int nt = 0; nt < 8; nt++) {
                int nb = (wn*64 + nt*8 + g) * LDK + koff + tig*2;
                b[nt][0] = *(const uint32_t*)(sB + nb);
                b[nt][1] = *(const uint32_t*)(sB + nb + 8);
            }
            #pragma unroll
            for (int mt = 0; mt < 4; mt++)
                #pragma unroll
                for (int nt = 0; nt < 8; nt++)
                    mma_f16a(acc[mt][nt], a[mt], b[nt][0], b[nt][1]);
        }
        __syncthreads();
    }
}

// QKV fused GEMM: blockIdx.z selects {Wq->Q, Wk->K, Wv->V}, head-layout fp16 out
__global__ void __launch_bounds__(256, 1) qkv_gemm(
    const __half* __restrict__ xh,
    const __half* __restrict__ wq, const __half* __restrict__ wk,
    const __half* __restrict__ wv,
    const float* __restrict__ bq, const float* __restrict__ bk,
    const float* __restrict__ bv,
    __half* __restrict__ qh, __half* __restrict__ kh, __half* __restrict__ vh)
{
    extern __shared__ __align__(16) __half sb[];
    const int z = blockIdx.z;
    const __half* W    = (z == 0) ? wq : (z == 1) ? wk : wv;
    const float*  bias = (z == 0) ? bq : (z == 1) ? bk : bv;
    __half* oh         = (z == 0) ? qh : (z == 1) ? kh : vh;

    const int tid = threadIdx.x;
    const int m0 = blockIdx.y * 128;
    const int n0 = blockIdx.x * 256;

    float acc[4][8][4];
    #pragma unroll
    for (int mt = 0; mt < 4; mt++)
        #pragma unroll
        for (int nt = 0; nt < 8; nt++)
            #pragma unroll
            for (int r = 0; r < 4; r++) acc[mt][nt][r] = 0.f;

    gemm_core(sb, xh, W, m0, n0, tid, acc);

    const int lane = tid & 31, g = lane >> 2, tig = lane & 3;
    const int wm = (tid >> 5) & 1, wn = (tid >> 5) >> 1;
    #pragma unroll
    for (int mt = 0; mt < 4; mt++) {
        #pragma unroll
        for (int nt = 0; nt < 8; nt++) {
            int col = n0 + wn*64 + nt*8 + tig*2;
            float2 bb = *(const float2*)(bias + col);
            int row = m0 + wm*64 + mt*16 + g;
            int h = col >> 6, dh = col & 63;
            int b0i = row >> 11, s0 = row & (SEQ - 1);
            int b1i = (row + 8) >> 11, s1 = (row + 8) & (SEQ - 1);
            size_t i0 = ((size_t)(b0i*NHEAD + h)*SEQ + s0)*DHEAD + dh;
            size_t i1 = ((size_t)(b1i*NHEAD + h)*SEQ + s1)*DHEAD + dh;
            *(uint32_t*)(oh + i0) = pack_f16x2(acc[mt][nt][0] + bb.x,
                                               acc[mt][nt][1] + bb.y);
            *(uint32_t*)(oh + i1) = pack_f16x2(acc[mt][nt][2] + bb.x,
                                               acc[mt][nt][3] + bb.y);
        }
    }
}

// Output GEMM: fp32 row-major out = gx @ Wo^T + bo
__global__ void __launch_bounds__(256, 1) out_gemm(
    const __half* __restrict__ A, const __half* __restrict__ Bh,
    const float* __restrict__ bias, float* __restrict__ C)
{
    extern __shared__ __align__(16) __half sb[];
    const int tid = threadIdx.x;
    const int m0 = blockIdx.y * 128;
    const int n0 = blockIdx.x * 256;

    float acc[4][8][4];
    #pragma unroll
    for (int mt = 0; mt < 4; mt++)
        #pragma unroll
        for (int nt = 0; nt < 8; nt++)
            #pragma unroll
            for (int r = 0; r < 4; r++) acc[mt][nt][r] = 0.f;

    gemm_core(sb, A, Bh, m0, n0, tid, acc);

    const int lane = tid & 31, g = lane >> 2, tig = lane & 3;
    const int wm = (tid >> 5) & 1, wn = (tid >> 5) >> 1;
    #pragma unroll
    for (int mt = 0; mt < 4; mt++) {
        #pragma unroll
        for (int nt = 0; nt < 8; nt++) {
            int col = n0 + wn*64 + nt*8 + tig*2;
            float2 bb = *(const float2*)(bias + col);
            int row = m0 + wm*64 + mt*16 + g;
            *(float2*)(C + (size_t)row * DMODEL + col) =
                make_float2(acc[mt][nt][0] + bb.x, acc[mt][nt][1] + bb.y);
            *(float2*)(C + (size_t)(row + 8) * DMODEL + col) =
                make_float2(acc[mt][nt][2] + bb.x, acc[mt][nt][3] + bb.y);
        }
    }
}

// ---------------------------------------------------------------------------
// fp16 HMMA flash attention (1-term).
// Grid (S/128, H, B), 256 thr = 8 warps x 16 q-rows. Log2-domain softmax,
// additive 0/-inf mask. fp16 output plane.
// ---------------------------------------------------------------------------
#define LQ 72
#define S_Q 0
#define S_STG (128*LQ)
#define ASTG  (2*128*LQ)                 // per stage: K + V
#define SM_HALF_ELEMS (S_STG + 2*ASTG)   // 46080 halves = 92160 B
#define SCL2E 0.1803368801111244f        // 0.125 * log2(e)

__global__ void __launch_bounds__(256, 1) attn_mma_kernel(
    const __half* __restrict__ qhg, const __half* __restrict__ khg,
    const __half* __restrict__ vhg, const float* __restrict__ mask,
    __half* __restrict__ xh)
{
    extern __shared__ __align__(16) __half sm[];
    float* fsec  = (float*)(sm + SM_HALF_ELEMS);
    float* madds = fsec;          // [2][128]
    float* mqs   = fsec + 256;    // [128]

    const int tid  = threadIdx.x;
    const int w    = tid >> 5;
    const int lane = tid & 31;
    const int g    = lane >> 2;
    const int tig  = lane & 3;
    const int q0 = blockIdx.x * 128;
    const int h  = blockIdx.y;
    const int b  = blockIdx.z;
    const size_t hb = ((size_t)(b*NHEAD + h)) * SEQ * DHEAD;

    {
        const __half* srcq = qhg + hb + (size_t)q0 * DHEAD;
        #pragma unroll
        for (int i = 0; i < 4; i++) {
            int lin = i*256 + tid;
            int r = lin >> 3, sgm = lin & 7;
            cp16(smem_u32(sm + S_Q + r*LQ + sgm*8), srcq + r*DHEAD + sgm*8);
        }
        if (tid < 128) mqs[tid] = mask[b*SEQ + q0 + tid];
    }

    auto load_stage = [&](int t) {
        int st = t & 1;
        const size_t jb = hb + (size_t)t * 128 * DHEAD;
        __half* dk = sm + S_STG + st * ASTG;
        #pragma unroll
        for (int i = 0; i < 4; i++) {
            int lin = i*256 + tid;
            int r = lin >> 3, sgm = lin & 7;
            int off = r*LQ + sgm*8;
            size_t go = (size_t)r*DHEAD + sgm*8;
            cp16(smem_u32(dk + off),          khg + jb + go);
            cp16(smem_u32(dk + 128*LQ + off), vhg + jb + go);
        }
        if (tid < 128) {
            float mv = mask[b*SEQ + t*128 + tid];
            madds[st*128 + tid] = (mv > 0.f) ? 0.f : -CUDART_INF_F;
        }
    };

    load_stage(0); cp_commit();
    load_stage(1); cp_commit();
    cp_wait<1>(); __syncthreads();

    uint32_t aq[4][4];
    #pragma unroll
    for (int ks = 0; ks < 4; ks++) {
        int base = (w*16 + g)*LQ + ks*16 + tig*2;
        aq[ks][0] = *(const uint32_t*)(sm + S_Q + base);
        aq[ks][1] = *(const uint32_t*)(sm + S_Q + base + 8*LQ);
        aq[ks][2] = *(const uint32_t*)(sm + S_Q + base + 8);
        aq[ks][3] = *(const uint32_t*)(sm + S_Q + base + 8*LQ + 8);
    }

    float o[8][4];
    #pragma unroll
    for (int dt = 0; dt < 8; dt++)
        #pragma unroll
        for (int j = 0; j < 4; j++) o[dt][j] = 0.f;
    float m0 = -CUDART_INF_F, m1 = -CUDART_INF_F, l0 = 0.f, l1 = 0.f;

    #pragma unroll 1
    for (int t = 0; t < SEQ/128; t++) {
        const __half* kh = sm + S_STG + (t & 1) * ASTG;
        const __half* vh = kh + 128*LQ;
        const float* ma = madds + (t & 1) * 128;

        // ---- scores = Q K^T ----
        float sc[16][4];
        #pragma unroll
        for (int nt = 0; nt < 16; nt++)
            #pragma unroll
            for (int j = 0; j < 4; j++) sc[nt][j] = 0.f;

        #pragma unroll
        for (int ks = 0; ks < 4; ks++) {
            #pragma unroll
            for (int nt = 0; nt < 16; nt++) {
                int nb = (nt*8 + g)*LQ + ks*16 + tig*2;
                uint32_t bh0 = *(const uint32_t*)(kh + nb);
                uint32_t bh1 = *(const uint32_t*)(kh + nb + 8);
                mma_f16a(sc[nt], aq[ks], bh0, bh1);
            }
        }

        // ---- masked online softmax (log2 domain) ----
        float nm0 = m0, nm1 = m1;
        #pragma unroll
        for (int nt = 0; nt < 16; nt++) {
            float2 mm = *(const float2*)(ma + nt*8 + tig*2);
            sc[nt][0] = fmaf(sc[nt][0], SCL2E, mm.x);
            sc[nt][1] = fmaf(sc[nt][1], SCL2E, mm.y);
            sc[nt][2] = fmaf(sc[nt][2], SCL2E, mm.x);
            sc[nt][3] = fmaf(sc[nt][3], SCL2E, mm.y);
            nm0 = fmaxf(nm0, fmaxf(sc[nt][0], sc[nt][1]));
            nm1 = fmaxf(nm1, fmaxf(sc[nt][2], sc[nt][3]));
        }
        nm0 = fmaxf(nm0, __shfl_xor_sync(0xffffffffu, nm0, 1));
        nm0 = fmaxf(nm0, __shfl_xor_sync(0xffffffffu, nm0, 2));
        nm1 = fmaxf(nm1, __shfl_xor_sync(0xffffffffu, nm1, 1));
        nm1 = fmaxf(nm1, __shfl_xor_sync(0xffffffffu, nm1, 2));
        float base0 = (nm0 == -CUDART_INF_F) ? 0.f : nm0;
        float base1 = (nm1 == -CUDART_INF_F) ? 0.f : nm1;
        float corr0 = ex2f(m0 - base0);
        float corr1 = ex2f(m1 - base1);

        float rs0 = 0.f, rs1 = 0.f;
        #pragma unroll
        for (int nt = 0; nt < 16; nt++) {
            sc[nt][0] = ex2f(sc[nt][0] - base0);
            sc[nt][1] = ex2f(sc[nt][1] - base0);
            sc[nt][2] = ex2f(sc[nt][2] - base1);
            sc[nt][3] = ex2f(sc[nt][3] - base1);
            rs0 += sc[nt][0] + sc[nt][1];
            rs1 += sc[nt][2] + sc[nt][3];
        }
        rs0 += __shfl_xor_sync(0xffffffffu, rs0, 1);
        rs0 += __shfl_xor_sync(0xffffffffu, rs0, 2);
        rs1 += __shfl_xor_sync(0xffffffffu, rs1, 1);
        rs1 += __shfl_xor_sync(0xffffffffu, rs1, 2);
        l0 = l0 * corr0 + rs0;
        l1 = l1 * corr1 + rs1;
        m0 = nm0; m1 = nm1;
        #pragma unroll
        for (int dt = 0; dt < 8; dt++) {
            o[dt][0] *= corr0; o[dt][1] *= corr0;
            o[dt][2] *= corr1; o[dt][3] *= corr1;
        }

        // ---- O += P V ; P packed register-direct ----
        const int vro = (lane & 15)*LQ + ((lane >> 4) << 3);
        #pragma unroll
        for (int ks = 0; ks < 8; ks++) {
            uint32_t ah[4];
            ah[0] = pack_f16x2(sc[2*ks][0],   sc[2*ks][1]);
            ah[1] = pack_f16x2(sc[2*ks][2],   sc[2*ks][3]);
            ah[2] = pack_f16x2(sc[2*ks+1][0], sc[2*ks+1][1]);
            ah[3] = pack_f16x2(sc[2*ks+1][2], sc[2*ks+1][3]);
            const int vbase = ks*16*LQ + vro;
            #pragma unroll
            for (int ntp = 0; ntp < 4; ntp++) {
                uint32_t bh0, bh1, bh2, bh3;
                LDSM4T(bh0, bh1, bh2, bh3, smem_u32(vh + vbase + ntp*16));
                mma_f16a(o[ntp*2],   ah, bh0, bh1);
                mma_f16a(o[ntp*2+1], ah, bh2, bh3);
            }
        }

        __syncthreads();
        if (t + 2 < SEQ/128) {
            load_stage(t + 2); cp_commit(); cp_wait<1>();
        } else {
            cp_wait<0>();
        }
        __syncthreads();
    }

    // ---- finalize: /l, zero masked query rows, write fp16 ----
    float inv0 = (mqs[w*16 + g]     > 0.f && l0 > 0.f) ? (1.f / l0) : 0.f;
    float inv1 = (mqs[w*16 + g + 8] > 0.f && l1 > 0.f) ? (1.f / l1) : 0.f;
    int r0 = q0 + w*16 + g;
    size_t o0b = ((size_t)b*SEQ + r0)     * DMODEL + h*DHEAD;
    size_t o1b = ((size_t)b*SEQ + r0 + 8) * DMODEL + h*DHEAD;
    #pragma unroll
    for (int dt = 0; dt < 8; dt++) {
        *(uint32_t*)(xh + o0b + dt*8 + tig*2) =
            pack_f16x2(o[dt][0]*inv0, o[dt][1]*inv0);
        *(uint32_t*)(xh + o1b + dt*8 + tig*2) =
            pack_f16x2(o[dt][2]*inv1, o[dt][3]*inv1);
    }
}

// ---------------------------------------------------------------------------
extern "C" void kernel_launch(void* const* d_in, const int* in_sizes, int n_in,
                              void* d_out, int out_size)
{
    const float* X    = (const float*)d_in[0];
    const float* mask = (const float*)d_in[1];
    const float* Wq   = (const float*)d_in[2];
    const float* bq   = (const float*)d_in[3];
    const float* Wk   = (const float*)d_in[4];
    const float* bk   = (const float*)d_in[5];
    const float* Wv   = (const float*)d_in[6];
    const float* bv   = (const float*)d_in[7];
    const float* Wo   = (const float*)d_in[8];
    const float* bo   = (const float*)d_in[9];
    float* out = (float*)d_out;

    __half *xh, *wq, *wk, *wv, *wo, *qh, *kh, *vh, *gxh;
    cudaGetSymbolAddress((void**)&xh,  g_xh);
    cudaGetSymbolAddress((void**)&wq,  g_wq);
    cudaGetSymbolAddress((void**)&wk,  g_wk);
    cudaGetSymbolAddress((void**)&wv,  g_wv);
    cudaGetSymbolAddress((void**)&wo,  g_wo);
    cudaGetSymbolAddress((void**)&qh,  g_qh);
    cudaGetSymbolAddress((void**)&kh,  g_kh);
    cudaGetSymbolAddress((void**)&vh,  g_vh);
    cudaGetSymbolAddress((void**)&gxh, g_gxh);

    const int gemm_smem = 2 * STAGE_ELEMS * 2;   // 61440 B
    cudaFuncSetAttribute(qkv_gemm, cudaFuncAttributeMaxDynamicSharedMemorySize, gemm_smem);
    cudaFuncSetAttribute(out_gemm, cudaFuncAttributeMaxDynamicSharedMemorySize, gemm_smem);

    const int attn_smem = SM_HALF_ELEMS*2 + (256 + 128)*4;   // 93696 B
    cudaFuncSetAttribute(attn_mma_kernel, cudaFuncAttributeMaxDynamicSharedMemorySize, attn_smem);

    const int ntot4 = NX4 + 4*NW4;               // 2097152
    split_all_kernel<<<ntot4/256, 256>>>(X, Wq, Wk, Wv, Wo,
                                         xh, wq, wk, wv, wo);

    dim3 gqkv(DMODEL/256, (BATCH*SEQ)/128, 3);   // (4, 32, 3)
    qkv_gemm<<<gqkv, 256, gemm_smem>>>(xh, wq, wk, wv, bq, bk, bv, qh, kh, vh);

    dim3 gattn(SEQ/128, NHEAD, BATCH);           // (16, 16, 2)
    attn_mma_kernel<<<gattn, 256, attn_smem>>>(qh, kh, vh, mask, gxh);

    dim3 gout(DMODEL/256, (BATCH*SEQ)/128);      // (4, 32)
    out_gemm<<<gout, 256, gemm_smem>>>(gxh, wo, bo, out);
}